// round 1
// baseline (speedup 1.0000x reference)
#include <cuda_runtime.h>
#include <math.h>

#define Bb   4
#define Tt   1024
#define BT   4096          // Bb*Tt tokens
#define DM   768
#define DI   1536
#define NH   24
#define HD   64
#define DS   16
#define CD   1568          // D_INNER + 2*D_STATE
#define DPJ  3128          // 2*DI + 2*DS + NH
#define DIN  80
#define LEPS 1e-5f

// ---------------- scratch (device globals; no allocations allowed) ----------
__device__ float g_h [BT*DM];
__device__ float g_hn[BT*DM];
__device__ float g_zx [2][BT*DPJ];
__device__ float g_xbc[2][BT*CD];
__device__ float g_dt [2][BT*NH];
__device__ float g_dA [2][BT*NH];
__device__ float g_y  [2][BT*DI];
__device__ float g_yn [2][BT*DI];
__device__ float g_o  [2][BT*DM];
__device__ int   g_mask_kind;   // 0=int32, 1=float32, 2=uint8/bool

// ---------------- helpers ----------------
__device__ __forceinline__ float block_sum(float v, float* sh) {
    int lane = threadIdx.x & 31, wid = threadIdx.x >> 5;
    #pragma unroll
    for (int o = 16; o > 0; o >>= 1) v += __shfl_xor_sync(0xffffffffu, v, o);
    if (lane == 0) sh[wid] = v;
    __syncthreads();
    int nw = (blockDim.x + 31) >> 5;
    if (threadIdx.x < 32) {
        float t = (threadIdx.x < nw) ? sh[threadIdx.x] : 0.f;
        #pragma unroll
        for (int o = 16; o > 0; o >>= 1) t += __shfl_xor_sync(0xffffffffu, t, o);
        if (threadIdx.x == 0) sh[0] = t;
    }
    __syncthreads();
    float r = sh[0];
    __syncthreads();
    return r;
}

__device__ __forceinline__ float rsqrt_acc(float a) {
    float r = rsqrtf(a);
    r = r * (1.5f - 0.5f * a * r * r);   // one Newton step
    return r;
}

__device__ __forceinline__ float silu_f(float v) {
    return v / (1.f + expf(-v));
}

// ---------------- mask dtype detector -----------
__global__ void detect_mask_k(const unsigned int* __restrict__ m) {
    __shared__ int s_ni, s_nf;
    if (threadIdx.x == 0) { s_ni = 0; s_nf = 0; }
    __syncthreads();
    int ni = 0, nf = 0;
    for (int i = threadIdx.x; i < 1024; i += blockDim.x) {   // only first 4096 bytes (safe)
        unsigned w = m[i];
        if (w != 0u && w != 1u)           ni = 1;
        if (w != 0u && w != 0x3F800000u)  nf = 1;
    }
    if (ni) atomicOr(&s_ni, 1);
    if (nf) atomicOr(&s_nf, 1);
    __syncthreads();
    if (threadIdx.x == 0)
        g_mask_kind = (!s_ni) ? 0 : ((!s_nf) ? 1 : 2);
}

__global__ void mask_apply_k(const void* __restrict__ maskp,
                             const float* __restrict__ mask_token) {
    int bt = blockIdx.x;
    int kind = g_mask_kind;
    bool is;
    if (kind == 0)      is = ((const int*)maskp)[bt] != 0;
    else if (kind == 1) is = ((const float*)maskp)[bt] != 0.f;
    else                is = ((const unsigned char*)maskp)[bt] != 0;
    if (is) g_h[bt * DM + threadIdx.x] = mask_token[threadIdx.x];
}

// ---------------- GEMM: C = A(MxK) @ B(KxN) + bias, row-major, fp32 ---------
// M multiple of 64, K multiple of 16. N arbitrary (guarded).
__global__ void gemm_bias_k(const float* __restrict__ A, const float* __restrict__ B,
                            const float* __restrict__ bias, float* __restrict__ C,
                            int M, int N, int K) {
    __shared__ float As[16][65];
    __shared__ float Bs[16][64];
    const int tid = threadIdx.x;
    const int tx = tid & 15, ty = tid >> 4;
    const int row0 = blockIdx.y * 64, col0 = blockIdx.x * 64;
    float acc[4][4] = {};
    for (int k0 = 0; k0 < K; k0 += 16) {
        #pragma unroll
        for (int i = 0; i < 4; i++) {
            int e = tid + 256 * i;
            int r = e >> 4, c = e & 15;
            As[c][r] = A[(size_t)(row0 + r) * K + (k0 + c)];
        }
        #pragma unroll
        for (int i = 0; i < 4; i++) {
            int e = tid + 256 * i;
            int r = e >> 6, c = e & 63;
            int col = col0 + c;
            Bs[r][c] = (col < N) ? B[(size_t)(k0 + r) * N + col] : 0.f;
        }
        __syncthreads();
        #pragma unroll
        for (int kk = 0; kk < 16; kk++) {
            float a0 = As[kk][ty * 4 + 0];
            float a1 = As[kk][ty * 4 + 1];
            float a2 = As[kk][ty * 4 + 2];
            float a3 = As[kk][ty * 4 + 3];
            float4 bv = *(const float4*)&Bs[kk][tx * 4];
            acc[0][0] = fmaf(a0, bv.x, acc[0][0]); acc[0][1] = fmaf(a0, bv.y, acc[0][1]);
            acc[0][2] = fmaf(a0, bv.z, acc[0][2]); acc[0][3] = fmaf(a0, bv.w, acc[0][3]);
            acc[1][0] = fmaf(a1, bv.x, acc[1][0]); acc[1][1] = fmaf(a1, bv.y, acc[1][1]);
            acc[1][2] = fmaf(a1, bv.z, acc[1][2]); acc[1][3] = fmaf(a1, bv.w, acc[1][3]);
            acc[2][0] = fmaf(a2, bv.x, acc[2][0]); acc[2][1] = fmaf(a2, bv.y, acc[2][1]);
            acc[2][2] = fmaf(a2, bv.z, acc[2][2]); acc[2][3] = fmaf(a2, bv.w, acc[2][3]);
            acc[3][0] = fmaf(a3, bv.x, acc[3][0]); acc[3][1] = fmaf(a3, bv.y, acc[3][1]);
            acc[3][2] = fmaf(a3, bv.z, acc[3][2]); acc[3][3] = fmaf(a3, bv.w, acc[3][3]);
        }
        __syncthreads();
    }
    #pragma unroll
    for (int i = 0; i < 4; i++) {
        int row = row0 + ty * 4 + i;
        #pragma unroll
        for (int j = 0; j < 4; j++) {
            int col = col0 + tx * 4 + j;
            if (col < N) {
                float bv = bias ? bias[col] : 0.f;
                C[(size_t)row * N + col] = acc[i][j] + bv;
            }
        }
    }
}

// ---------------- LayerNorm over 768, one block per token -------------------
__global__ void layernorm_k(const float* __restrict__ in, const float* __restrict__ w,
                            const float* __restrict__ b, float* __restrict__ out) {
    __shared__ float sh[32];
    int row = blockIdx.x;
    const float* x = in + (size_t)row * DM;
    int t = threadIdx.x;  // 256 threads, 3 elems each
    float v0 = x[t], v1 = x[t + 256], v2 = x[t + 512];
    float S  = block_sum(v0 + v1 + v2, sh);
    float mu = S * (1.f / DM);
    float d0 = v0 - mu, d1 = v1 - mu, d2 = v2 - mu;
    float S2 = block_sum(d0 * d0 + d1 * d1 + d2 * d2, sh);
    float inv = rsqrt_acc(S2 * (1.f / DM) + LEPS);
    float* o = out + (size_t)row * DM;
    o[t]       = d0 * inv * w[t]       + b[t];
    o[t + 256] = d1 * inv * w[t + 256] + b[t + 256];
    o[t + 512] = d2 * inv * w[t + 512] + b[t + 512];
}

// ---------------- depthwise causal conv7 + silu (both dirs via blockIdx.y) --
__global__ void conv_silu_k(const float* __restrict__ cw, const float* __restrict__ cb, int l) {
    int d = blockIdx.y;
    int idx = blockIdx.x * 256 + threadIdx.x;    // over BT*CD
    if (idx >= BT * CD) return;
    int c = idx % CD;
    int btt = idx / CD;
    int b = btt >> 10, t = btt & 1023;
    const float* w = cw + ((size_t)(l * 2 + d) * CD + c) * 7;
    float acc = cb[(l * 2 + d) * CD + c];
    const float* src = g_zx[d];
    if (d == 0) {
        #pragma unroll
        for (int k = 0; k < 7; k++) {
            int tt = t - 6 + k;
            if (tt >= 0) acc = fmaf(w[k], src[(size_t)(b * Tt + tt) * DPJ + 1536 + c], acc);
        }
    } else {
        #pragma unroll
        for (int k = 0; k < 7; k++) {
            int tt = t + 6 - k;
            if (tt < Tt) acc = fmaf(w[k], src[(size_t)(b * Tt + tt) * DPJ + 1536 + c], acc);
        }
    }
    g_xbc[d][idx] = silu_f(acc);
}

// ---------------- dt: softplus + dA = exp(-exp(A)*dt) -----------------------
__global__ void dt_prep_k(const float* __restrict__ dt_bias, const float* __restrict__ A_log, int l) {
    int d = blockIdx.y;
    int idx = blockIdx.x * 256 + threadIdx.x;    // over BT*NH
    int h = idx % NH;
    int bt = idx / NH;
    float raw = g_zx[d][(size_t)bt * DPJ + 3104 + h] + dt_bias[(l * 2 + d) * NH + h];
    float dt = (raw > 20.f) ? raw : log1pf(expf(raw));
    float a = -expf(A_log[(l * 2 + d) * NH + h]);
    g_dt[d][idx] = dt;
    g_dA[d][idx] = expf(a * dt);
}

// ---------------- sequential SSM scan: one block per (b, head, dir) ---------
__global__ void scan_k(const float* __restrict__ Dp, int l) {
    const int d  = blockIdx.y;
    const int bh = blockIdx.x;            // 0..95
    const int b  = bh / NH, hh = bh % NH;
    const int p  = threadIdx.x;           // 0..63
    const float* __restrict__ xbc = g_xbc[d];
    const float* __restrict__ dtp = g_dt[d];
    const float* __restrict__ dAp = g_dA[d];
    float* __restrict__ yb = g_y[d];
    const float Dc = Dp[(l * 2 + d) * NH + hh];
    float s[16];
    #pragma unroll
    for (int n = 0; n < 16; n++) s[n] = 0.f;
    for (int i = 0; i < Tt; i++) {
        int t  = d ? (Tt - 1 - i) : i;
        int bt = b * Tt + t;
        const float* row = xbc + (size_t)bt * CD;
        float x  = row[hh * HD + p];
        float dt = dtp[bt * NH + hh];
        float dA = dAp[bt * NH + hh];
        float Bv[16], Cv[16];
        #pragma unroll
        for (int q = 0; q < 4; q++) {
            *(float4*)&Bv[q * 4] = *(const float4*)(row + 1536 + q * 4);
            *(float4*)&Cv[q * 4] = *(const float4*)(row + 1552 + q * 4);
        }
        float c0 = dt * x;
        float a0 = 0.f, a1 = 0.f, a2 = 0.f, a3 = 0.f;
        #pragma unroll
        for (int n = 0; n < 16; n += 4) {
            s[n + 0] = fmaf(s[n + 0], dA, c0 * Bv[n + 0]); a0 = fmaf(s[n + 0], Cv[n + 0], a0);
            s[n + 1] = fmaf(s[n + 1], dA, c0 * Bv[n + 1]); a1 = fmaf(s[n + 1], Cv[n + 1], a1);
            s[n + 2] = fmaf(s[n + 2], dA, c0 * Bv[n + 2]); a2 = fmaf(s[n + 2], Cv[n + 2], a2);
            s[n + 3] = fmaf(s[n + 3], dA, c0 * Bv[n + 3]); a3 = fmaf(s[n + 3], Cv[n + 3], a3);
        }
        yb[(size_t)bt * DI + hh * HD + p] = (a0 + a1) + (a2 + a3) + Dc * x;
    }
}

// ---------------- gated RMS norm over 1536 ----------------------------------
__global__ void gated_rms_k(const float* __restrict__ ssm_w, int l) {
    __shared__ float sh[32];
    int d = blockIdx.y;
    int row = blockIdx.x;
    const float* y = g_y[d] + (size_t)row * DI;
    const float* z = g_zx[d] + (size_t)row * DPJ;     // z = first DI cols
    float* out = g_yn[d] + (size_t)row * DI;
    const float* w = ssm_w + (l * 2 + d) * DI;
    int t = threadIdx.x;   // 256 threads, 6 elems each
    float g[6], s2 = 0.f;
    #pragma unroll
    for (int i = 0; i < 6; i++) {
        int c = t + 256 * i;
        float gv = y[c] * silu_f(z[c]);
        g[i] = gv;
        s2 += gv * gv;
    }
    float S2 = block_sum(s2, sh);
    float inv = rsqrt_acc(S2 * (1.f / DI) + LEPS);
    #pragma unroll
    for (int i = 0; i < 6; i++) {
        int c = t + 256 * i;
        out[c] = g[i] * inv * w[c];
    }
}

// ---------------- residual add: h += o0 + o1 --------------------------------
__global__ void add3_k() {
    int i = blockIdx.x * 256 + threadIdx.x;
    g_h[i] += g_o[0][i] + g_o[1][i];
}

__global__ void copy_k(const float* __restrict__ src, float* __restrict__ dst, int n) {
    int i = blockIdx.x * 256 + threadIdx.x;
    if (i < n) dst[i] = src[i];
}

// ---------------- launcher ---------------------------------------------------
extern "C" void kernel_launch(void* const* d_in, const int* in_sizes, int n_in,
                              void* d_out, int out_size) {
    const float* x          = (const float*)d_in[0];
    const void*  maskp      = d_in[1];
    const float* proj_in_w  = (const float*)d_in[2];
    const float* proj_in_b  = (const float*)d_in[3];
    const float* mask_token = (const float*)d_in[4];
    const float* ln_w       = (const float*)d_in[5];
    const float* ln_b       = (const float*)d_in[6];
    const float* in_proj_w  = (const float*)d_in[7];
    const float* in_proj_b  = (const float*)d_in[8];
    const float* conv_w     = (const float*)d_in[9];
    const float* conv_b     = (const float*)d_in[10];
    const float* dt_bias    = (const float*)d_in[11];
    const float* A_log      = (const float*)d_in[12];
    const float* Dp         = (const float*)d_in[13];
    const float* ssm_w      = (const float*)d_in[14];
    const float* out_proj_w = (const float*)d_in[15];
    const float* fn_w       = (const float*)d_in[16];
    const float* fn_b       = (const float*)d_in[17];
    const float* proj_out_w = (const float*)d_in[18];
    const float* proj_out_b = (const float*)d_in[19];
    float* out = (float*)d_out;

    float *p_h, *p_hn, *p_zx, *p_yn, *p_o;
    cudaGetSymbolAddress((void**)&p_h,  g_h);
    cudaGetSymbolAddress((void**)&p_hn, g_hn);
    cudaGetSymbolAddress((void**)&p_zx, g_zx);
    cudaGetSymbolAddress((void**)&p_yn, g_yn);
    cudaGetSymbolAddress((void**)&p_o,  g_o);

    detect_mask_k<<<1, 256>>>((const unsigned int*)maskp);

    // h = x @ proj_in_w + b ; apply mask token
    gemm_bias_k<<<dim3(DM / 64, BT / 64), 256>>>(x, proj_in_w, proj_in_b, p_h, BT, DM, DIN);
    mask_apply_k<<<BT, DM>>>(maskp, mask_token);

    for (int l = 0; l < 2; l++) {
        layernorm_k<<<BT, 256>>>(p_h, ln_w + l * DM, ln_b + l * DM, p_hn);
        for (int d = 0; d < 2; d++) {
            gemm_bias_k<<<dim3((DPJ + 63) / 64, BT / 64), 256>>>(
                p_hn,
                in_proj_w + (size_t)(l * 2 + d) * DM * DPJ,
                in_proj_b + (size_t)(l * 2 + d) * DPJ,
                p_zx + (size_t)d * BT * DPJ, BT, DPJ, DM);
        }
        conv_silu_k<<<dim3((BT * CD + 255) / 256, 2), 256>>>(conv_w, conv_b, l);
        dt_prep_k<<<dim3(BT * NH / 256, 2), 256>>>(dt_bias, A_log, l);
        scan_k<<<dim3(Bb * NH, 2), HD>>>(Dp, l);
        gated_rms_k<<<dim3(BT, 2), 256>>>(ssm_w, l);
        for (int d = 0; d < 2; d++) {
            gemm_bias_k<<<dim3(DM / 64, BT / 64), 256>>>(
                p_yn + (size_t)d * BT * DI,
                out_proj_w + (size_t)(l * 2 + d) * DI * DM,
                nullptr,
                p_o + (size_t)d * BT * DM, BT, DM, DI);
        }
        add3_k<<<BT * DM / 256, 256>>>();
    }

    // hidden = layernorm(h, final) -> g_hn ; outputs
    layernorm_k<<<BT, 256>>>(p_h, fn_w, fn_b, p_hn);

    const int PRED = BT * DIN, HID = BT * DM;
    float* predp = nullptr;
    float* hidp  = nullptr;
    if (out_size >= PRED + HID)      { predp = out; hidp = out + PRED; }
    else if (out_size == PRED)       { predp = out; }
    else                             { hidp = out; }

    if (hidp)
        copy_k<<<(HID + 255) / 256, 256>>>(p_hn, hidp, HID);
    if (predp)
        gemm_bias_k<<<dim3((DIN + 63) / 64, BT / 64), 256>>>(
            p_hn, proj_out_w, proj_out_b, predp, BT, DIN, DM);
}

// round 3
// speedup vs baseline: 1.6425x; 1.6425x over previous
#include <cuda_runtime.h>
#include <cuda_bf16.h>
#include <math.h>
#include <stdint.h>

#define Bb   4
#define Tt   1024
#define BT   4096          // Bb*Tt tokens
#define DM   768
#define DI   1536
#define NH   24
#define HD   64
#define DS   16
#define CD   1568          // D_INNER + 2*D_STATE
#define DPJ  3128          // 2*DI + 2*DS + NH
#define DIN  80
#define LEPS 1e-5f

// ---------------- scratch (device globals; no allocations allowed) ----------
__device__ float g_h [BT*DM];
__device__ float g_hn[BT*DM];
__device__ float g_zx [2][BT*DPJ];
__device__ float g_xbc[2][BT*CD];
__device__ float g_dt [2][BT*NH];
__device__ float g_dA [2][BT*NH];
__device__ float g_y  [2][BT*DI];
__device__ float g_yn [2][BT*DI];
__device__ float g_o  [2][BT*DM];
__device__ int   g_mask_kind;   // 0=int32, 1=float32, 2=uint8/bool
// transposed weights [N,K] row-major
__device__ float g_wt_in [4][DPJ*DM];   // in_proj_w^T  (3128 x 768) x4
__device__ float g_wt_out[4][DM*DI];    // out_proj_w^T (768 x 1536) x4
__device__ float g_wt_pi [DM*DIN];      // proj_in_w^T  (768 x 80)
__device__ float g_wt_po [DIN*DM];      // proj_out_w^T (80 x 768)

// ---------------- generic helpers ----------------
__device__ __forceinline__ float block_sum(float v, float* sh) {
    int lane = threadIdx.x & 31, wid = threadIdx.x >> 5;
    #pragma unroll
    for (int o = 16; o > 0; o >>= 1) v += __shfl_xor_sync(0xffffffffu, v, o);
    if (lane == 0) sh[wid] = v;
    __syncthreads();
    int nw = (blockDim.x + 31) >> 5;
    if (threadIdx.x < 32) {
        float t = (threadIdx.x < nw) ? sh[threadIdx.x] : 0.f;
        #pragma unroll
        for (int o = 16; o > 0; o >>= 1) t += __shfl_xor_sync(0xffffffffu, t, o);
        if (threadIdx.x == 0) sh[0] = t;
    }
    __syncthreads();
    float r = sh[0];
    __syncthreads();
    return r;
}

__device__ __forceinline__ float rsqrt_acc(float a) {
    float r = rsqrtf(a);
    r = r * (1.5f - 0.5f * a * r * r);
    return r;
}

__device__ __forceinline__ float silu_f(float v) {
    return v / (1.f + expf(-v));
}

// ---------------- tensor-core GEMM via legacy mma.sync (bf16x3 split) -------
// C[M,N] = A[M,K] @ Bt[N,K]^T + bias.  M multiple of 128. N,K even.
// CTA: 128x128 tile, 256 threads (8 warps, 2x4), warp tile 64x32.
// SMEM per buffer: A_hi/A_lo/B_hi/B_lo each [128][40] bf16 (padded rows).

#define SAS   40          // bf16 row stride in smem
#define QLEN  (128*SAS)   // 5120 bf16 elems per quarter
#define BUFE  (4*QLEN)    // 20480 bf16 per buffer
#define TG_SMEM (2*BUFE*2)  // bytes: 2 buffers * 20480 elems * 2B = 81920

#define MMA16816(acc, a, b) \
    asm volatile("mma.sync.aligned.m16n8k16.row.col.f32.bf16.bf16.f32 " \
        "{%0,%1,%2,%3},{%4,%5,%6,%7},{%8,%9},{%0,%1,%2,%3};" \
        : "+f"((acc)[0]), "+f"((acc)[1]), "+f"((acc)[2]), "+f"((acc)[3]) \
        : "r"((a)[0]), "r"((a)[1]), "r"((a)[2]), "r"((a)[3]), \
          "r"((b)[0]), "r"((b)[1]))

__global__ __launch_bounds__(256, 1)
void tgemm_k(const float* __restrict__ A, const float* __restrict__ Bt,
             const float* __restrict__ bias, float* __restrict__ C,
             int N, int K) {
    extern __shared__ __nv_bfloat16 sm[];
    const int tid  = threadIdx.x;
    const int lane = tid & 31, warp = tid >> 5;
    const int wr = warp >> 2, wc = warp & 3;
    const int gid = lane >> 2, tq = lane & 3;
    const int row0 = blockIdx.y * 128, n0 = blockIdx.x * 128;

    float acc[4][4][4];
    #pragma unroll
    for (int mi = 0; mi < 4; mi++)
        #pragma unroll
        for (int ni = 0; ni < 4; ni++)
            #pragma unroll
            for (int e = 0; e < 4; e++) acc[mi][ni][e] = 0.f;

    const int nst = (K + 31) >> 5;
    float4 av[4], bv[4];

    auto gload = [&](int s) {
        const int k0 = s * 32;
        #pragma unroll
        for (int i = 0; i < 4; i++) {
            int task = i * 256 + tid, r = task >> 3, c4 = task & 7;
            int k = k0 + c4 * 4;
            av[i] = make_float4(0.f, 0.f, 0.f, 0.f);
            bv[i] = make_float4(0.f, 0.f, 0.f, 0.f);
            if (k < K)
                av[i] = *(const float4*)(A + (size_t)(row0 + r) * K + k);
            int n = n0 + r;
            if (k < K && n < N)
                bv[i] = *(const float4*)(Bt + (size_t)n * K + k);
        }
    };

    auto sstore = [&](int buf) {
        __nv_bfloat16* sa = sm + buf * BUFE;
        #pragma unroll
        for (int i = 0; i < 4; i++) {
            int task = i * 256 + tid, r = task >> 3, c4 = task & 7;
            int off = r * SAS + c4 * 4;
            float4 v = av[i];
            __nv_bfloat16 h0 = __float2bfloat16_rn(v.x);
            __nv_bfloat16 h1 = __float2bfloat16_rn(v.y);
            __nv_bfloat16 h2 = __float2bfloat16_rn(v.z);
            __nv_bfloat16 h3 = __float2bfloat16_rn(v.w);
            __nv_bfloat16 l0 = __float2bfloat16_rn(v.x - __bfloat162float(h0));
            __nv_bfloat16 l1 = __float2bfloat16_rn(v.y - __bfloat162float(h1));
            __nv_bfloat16 l2 = __float2bfloat16_rn(v.z - __bfloat162float(h2));
            __nv_bfloat16 l3 = __float2bfloat16_rn(v.w - __bfloat162float(h3));
            *(__nv_bfloat162*)(sa + off)              = __nv_bfloat162(h0, h1);
            *(__nv_bfloat162*)(sa + off + 2)          = __nv_bfloat162(h2, h3);
            *(__nv_bfloat162*)(sa + QLEN + off)       = __nv_bfloat162(l0, l1);
            *(__nv_bfloat162*)(sa + QLEN + off + 2)   = __nv_bfloat162(l2, l3);
            float4 w = bv[i];
            __nv_bfloat16 p0 = __float2bfloat16_rn(w.x);
            __nv_bfloat16 p1 = __float2bfloat16_rn(w.y);
            __nv_bfloat16 p2 = __float2bfloat16_rn(w.z);
            __nv_bfloat16 p3 = __float2bfloat16_rn(w.w);
            __nv_bfloat16 q0 = __float2bfloat16_rn(w.x - __bfloat162float(p0));
            __nv_bfloat16 q1 = __float2bfloat16_rn(w.y - __bfloat162float(p1));
            __nv_bfloat16 q2 = __float2bfloat16_rn(w.z - __bfloat162float(p2));
            __nv_bfloat16 q3 = __float2bfloat16_rn(w.w - __bfloat162float(p3));
            *(__nv_bfloat162*)(sa + 2 * QLEN + off)      = __nv_bfloat162(p0, p1);
            *(__nv_bfloat162*)(sa + 2 * QLEN + off + 2)  = __nv_bfloat162(p2, p3);
            *(__nv_bfloat162*)(sa + 3 * QLEN + off)      = __nv_bfloat162(q0, q1);
            *(__nv_bfloat162*)(sa + 3 * QLEN + off + 2)  = __nv_bfloat162(q2, q3);
        }
    };

    auto compute = [&](int buf) {
        const __nv_bfloat16* sa = sm + buf * BUFE;
        const __nv_bfloat16* sb = sa + 2 * QLEN;
        #pragma unroll
        for (int kk = 0; kk < 32; kk += 16) {
            const int c = kk + tq * 2;
            uint32_t ah[4][4], al[4][4], bh[4][2], bl[4][2];
            #pragma unroll
            for (int mi = 0; mi < 4; mi++) {
                int r = wr * 64 + mi * 16 + gid;
                const __nv_bfloat16* p = sa + r * SAS + c;
                ah[mi][0] = *(const uint32_t*)(p);
                ah[mi][1] = *(const uint32_t*)(p + 8 * SAS);
                ah[mi][2] = *(const uint32_t*)(p + 8);
                ah[mi][3] = *(const uint32_t*)(p + 8 * SAS + 8);
                const __nv_bfloat16* q = p + QLEN;
                al[mi][0] = *(const uint32_t*)(q);
                al[mi][1] = *(const uint32_t*)(q + 8 * SAS);
                al[mi][2] = *(const uint32_t*)(q + 8);
                al[mi][3] = *(const uint32_t*)(q + 8 * SAS + 8);
            }
            #pragma unroll
            for (int ni = 0; ni < 4; ni++) {
                int n = wc * 32 + ni * 8 + gid;
                const __nv_bfloat16* p = sb + n * SAS + c;
                bh[ni][0] = *(const uint32_t*)(p);
                bh[ni][1] = *(const uint32_t*)(p + 8);
                const __nv_bfloat16* q = p + QLEN;
                bl[ni][0] = *(const uint32_t*)(q);
                bl[ni][1] = *(const uint32_t*)(q + 8);
            }
            #pragma unroll
            for (int mi = 0; mi < 4; mi++)
                #pragma unroll
                for (int ni = 0; ni < 4; ni++) {
                    MMA16816(acc[mi][ni], ah[mi], bh[ni]);
                    MMA16816(acc[mi][ni], ah[mi], bl[ni]);
                    MMA16816(acc[mi][ni], al[mi], bh[ni]);
                }
        }
    };

    gload(0);
    sstore(0);
    __syncthreads();
    for (int s = 0; s < nst; s++) {
        const int buf = s & 1;
        if (s + 1 < nst) gload(s + 1);
        compute(buf);
        if (s + 1 < nst) sstore(buf ^ 1);
        __syncthreads();
    }

    // epilogue: write fragments + bias
    #pragma unroll
    for (int mi = 0; mi < 4; mi++) {
        int row = row0 + wr * 64 + mi * 16 + gid;
        #pragma unroll
        for (int ni = 0; ni < 4; ni++) {
            int col = n0 + wc * 32 + ni * 8 + tq * 2;
            if (col < N) {
                float b0 = bias ? bias[col]     : 0.f;
                float b1 = bias ? bias[col + 1] : 0.f;
                float* c0 = C + (size_t)row * N + col;
                c0[0] = acc[mi][ni][0] + b0;
                c0[1] = acc[mi][ni][1] + b1;
                float* c1 = C + (size_t)(row + 8) * N + col;
                c1[0] = acc[mi][ni][2] + b0;
                c1[1] = acc[mi][ni][3] + b1;
            }
        }
    }
}

// ---------------- weight transpose: src[R,C] -> dst[C,R] ---------------------
__global__ void transpose_k(const float* __restrict__ src, float* __restrict__ dst,
                            int R, int C) {
    __shared__ float tile[32][33];
    int c0 = blockIdx.x * 32, r0 = blockIdx.y * 32;
    int x = c0 + threadIdx.x;
    #pragma unroll
    for (int j = threadIdx.y; j < 32; j += 8) {
        int r = r0 + j;
        tile[j][threadIdx.x] = (r < R && x < C) ? src[(size_t)r * C + x] : 0.f;
    }
    __syncthreads();
    int xr = r0 + threadIdx.x;
    #pragma unroll
    for (int j = threadIdx.y; j < 32; j += 8) {
        int c = c0 + j;
        if (c < C && xr < R) dst[(size_t)c * R + xr] = tile[threadIdx.x][j];
    }
}

// ---------------- mask dtype detector -----------
__global__ void detect_mask_k(const unsigned int* __restrict__ m) {
    __shared__ int s_ni, s_nf;
    if (threadIdx.x == 0) { s_ni = 0; s_nf = 0; }
    __syncthreads();
    int ni = 0, nf = 0;
    for (int i = threadIdx.x; i < 1024; i += blockDim.x) {
        unsigned w = m[i];
        if (w != 0u && w != 1u)           ni = 1;
        if (w != 0u && w != 0x3F800000u)  nf = 1;
    }
    if (ni) atomicOr(&s_ni, 1);
    if (nf) atomicOr(&s_nf, 1);
    __syncthreads();
    if (threadIdx.x == 0)
        g_mask_kind = (!s_ni) ? 0 : ((!s_nf) ? 1 : 2);
}

__global__ void mask_apply_k(const void* __restrict__ maskp,
                             const float* __restrict__ mask_token) {
    int bt = blockIdx.x;
    int kind = g_mask_kind;
    bool is;
    if (kind == 0)      is = ((const int*)maskp)[bt] != 0;
    else if (kind == 1) is = ((const float*)maskp)[bt] != 0.f;
    else                is = ((const unsigned char*)maskp)[bt] != 0;
    if (is) g_h[bt * DM + threadIdx.x] = mask_token[threadIdx.x];
}

// ---------------- LayerNorm over 768, one block per token -------------------
__global__ void layernorm_k(const float* __restrict__ in, const float* __restrict__ w,
                            const float* __restrict__ b, float* __restrict__ out) {
    __shared__ float sh[32];
    int row = blockIdx.x;
    const float* x = in + (size_t)row * DM;
    int t = threadIdx.x;
    float v0 = x[t], v1 = x[t + 256], v2 = x[t + 512];
    float S  = block_sum(v0 + v1 + v2, sh);
    float mu = S * (1.f / DM);
    float d0 = v0 - mu, d1 = v1 - mu, d2 = v2 - mu;
    float S2 = block_sum(d0 * d0 + d1 * d1 + d2 * d2, sh);
    float inv = rsqrt_acc(S2 * (1.f / DM) + LEPS);
    float* o = out + (size_t)row * DM;
    o[t]       = d0 * inv * w[t]       + b[t];
    o[t + 256] = d1 * inv * w[t + 256] + b[t + 256];
    o[t + 512] = d2 * inv * w[t + 512] + b[t + 512];
}

// ---------------- depthwise causal conv7 + silu (both dirs) -----------------
__global__ void conv_silu_k(const float* __restrict__ cw, const float* __restrict__ cb, int l) {
    int d = blockIdx.y;
    int idx = blockIdx.x * 256 + threadIdx.x;
    if (idx >= BT * CD) return;
    int c = idx % CD;
    int btt = idx / CD;
    int b = btt >> 10, t = btt & 1023;
    const float* w = cw + ((size_t)(l * 2 + d) * CD + c) * 7;
    float acc = cb[(l * 2 + d) * CD + c];
    const float* src = g_zx[d];
    if (d == 0) {
        #pragma unroll
        for (int k = 0; k < 7; k++) {
            int tt = t - 6 + k;
            if (tt >= 0) acc = fmaf(w[k], src[(size_t)(b * Tt + tt) * DPJ + 1536 + c], acc);
        }
    } else {
        #pragma unroll
        for (int k = 0; k < 7; k++) {
            int tt = t + 6 - k;
            if (tt < Tt) acc = fmaf(w[k], src[(size_t)(b * Tt + tt) * DPJ + 1536 + c], acc);
        }
    }
    g_xbc[d][idx] = silu_f(acc);
}

// ---------------- dt: softplus + dA ------------------------------------------
__global__ void dt_prep_k(const float* __restrict__ dt_bias, const float* __restrict__ A_log, int l) {
    int d = blockIdx.y;
    int idx = blockIdx.x * 256 + threadIdx.x;
    int h = idx % NH;
    int bt = idx / NH;
    float raw = g_zx[d][(size_t)bt * DPJ + 3104 + h] + dt_bias[(l * 2 + d) * NH + h];
    float dt = (raw > 20.f) ? raw : log1pf(expf(raw));
    float a = -expf(A_log[(l * 2 + d) * NH + h]);
    g_dt[d][idx] = dt;
    g_dA[d][idx] = expf(a * dt);
}

// ---------------- sequential SSM scan: one block per (b, head, dir) ---------
__global__ void scan_k(const float* __restrict__ Dp, int l) {
    const int d  = blockIdx.y;
    const int bh = blockIdx.x;
    const int b  = bh / NH, hh = bh % NH;
    const int p  = threadIdx.x;
    const float* __restrict__ xbc = g_xbc[d];
    const float* __restrict__ dtp = g_dt[d];
    const float* __restrict__ dAp = g_dA[d];
    float* __restrict__ yb = g_y[d];
    const float Dc = Dp[(l * 2 + d) * NH + hh];
    float s[16];
    #pragma unroll
    for (int n = 0; n < 16; n++) s[n] = 0.f;
    for (int i = 0; i < Tt; i++) {
        int t  = d ? (Tt - 1 - i) : i;
        int bt = b * Tt + t;
        const float* row = xbc + (size_t)bt * CD;
        float x  = row[hh * HD + p];
        float dt = dtp[bt * NH + hh];
        float dA = dAp[bt * NH + hh];
        float Bv[16], Cv[16];
        #pragma unroll
        for (int q = 0; q < 4; q++) {
            *(float4*)&Bv[q * 4] = *(const float4*)(row + 1536 + q * 4);
            *(float4*)&Cv[q * 4] = *(const float4*)(row + 1552 + q * 4);
        }
        float c0 = dt * x;
        float a0 = 0.f, a1 = 0.f, a2 = 0.f, a3 = 0.f;
        #pragma unroll
        for (int n = 0; n < 16; n += 4) {
            s[n + 0] = fmaf(s[n + 0], dA, c0 * Bv[n + 0]); a0 = fmaf(s[n + 0], Cv[n + 0], a0);
            s[n + 1] = fmaf(s[n + 1], dA, c0 * Bv[n + 1]); a1 = fmaf(s[n + 1], Cv[n + 1], a1);
            s[n + 2] = fmaf(s[n + 2], dA, c0 * Bv[n + 2]); a2 = fmaf(s[n + 2], Cv[n + 2], a2);
            s[n + 3] = fmaf(s[n + 3], dA, c0 * Bv[n + 3]); a3 = fmaf(s[n + 3], Cv[n + 3], a3);
        }
        yb[(size_t)bt * DI + hh * HD + p] = (a0 + a1) + (a2 + a3) + Dc * x;
    }
}

// ---------------- gated RMS norm over 1536 ----------------------------------
__global__ void gated_rms_k(const float* __restrict__ ssm_w, int l) {
    __shared__ float sh[32];
    int d = blockIdx.y;
    int row = blockIdx.x;
    const float* y = g_y[d] + (size_t)row * DI;
    const float* z = g_zx[d] + (size_t)row * DPJ;
    float* out = g_yn[d] + (size_t)row * DI;
    const float* w = ssm_w + (l * 2 + d) * DI;
    int t = threadIdx.x;
    float g[6], s2 = 0.f;
    #pragma unroll
    for (int i = 0; i < 6; i++) {
        int c = t + 256 * i;
        float gv = y[c] * silu_f(z[c]);
        g[i] = gv;
        s2 += gv * gv;
    }
    float S2 = block_sum(s2, sh);
    float inv = rsqrt_acc(S2 * (1.f / DI) + LEPS);
    #pragma unroll
    for (int i = 0; i < 6; i++) {
        int c = t + 256 * i;
        out[c] = g[i] * inv * w[c];
    }
}

// ---------------- residual add: h += o0 + o1 --------------------------------
__global__ void add3_k() {
    int i = blockIdx.x * 256 + threadIdx.x;
    g_h[i] += g_o[0][i] + g_o[1][i];
}

__global__ void copy_k(const float* __restrict__ src, float* __restrict__ dst, int n) {
    int i = blockIdx.x * 256 + threadIdx.x;
    if (i < n) dst[i] = src[i];
}

// ---------------- launcher ---------------------------------------------------
extern "C" void kernel_launch(void* const* d_in, const int* in_sizes, int n_in,
                              void* d_out, int out_size) {
    const float* x          = (const float*)d_in[0];
    const void*  maskp      = d_in[1];
    const float* proj_in_w  = (const float*)d_in[2];
    const float* proj_in_b  = (const float*)d_in[3];
    const float* mask_token = (const float*)d_in[4];
    const float* ln_w       = (const float*)d_in[5];
    const float* ln_b       = (const float*)d_in[6];
    const float* in_proj_w  = (const float*)d_in[7];
    const float* in_proj_b  = (const float*)d_in[8];
    const float* conv_w     = (const float*)d_in[9];
    const float* conv_b     = (const float*)d_in[10];
    const float* dt_bias    = (const float*)d_in[11];
    const float* A_log      = (const float*)d_in[12];
    const float* Dp         = (const float*)d_in[13];
    const float* ssm_w      = (const float*)d_in[14];
    const float* out_proj_w = (const float*)d_in[15];
    const float* fn_w       = (const float*)d_in[16];
    const float* fn_b       = (const float*)d_in[17];
    const float* proj_out_w = (const float*)d_in[18];
    const float* proj_out_b = (const float*)d_in[19];
    float* out = (float*)d_out;

    float *p_h, *p_hn, *p_zx, *p_yn, *p_o;
    float *p_wti, *p_wto, *p_wpi, *p_wpo;
    cudaGetSymbolAddress((void**)&p_h,   g_h);
    cudaGetSymbolAddress((void**)&p_hn,  g_hn);
    cudaGetSymbolAddress((void**)&p_zx,  g_zx);
    cudaGetSymbolAddress((void**)&p_yn,  g_yn);
    cudaGetSymbolAddress((void**)&p_o,   g_o);
    cudaGetSymbolAddress((void**)&p_wti, g_wt_in);
    cudaGetSymbolAddress((void**)&p_wto, g_wt_out);
    cudaGetSymbolAddress((void**)&p_wpi, g_wt_pi);
    cudaGetSymbolAddress((void**)&p_wpo, g_wt_po);

    cudaFuncSetAttribute(tgemm_k, cudaFuncAttributeMaxDynamicSharedMemorySize, TG_SMEM);

    detect_mask_k<<<1, 256>>>((const unsigned int*)maskp);

    // weight transposes (src[R,C] -> dst[C,R])
    {
        dim3 tb(32, 8);
        // proj_in_w: [DIN, DM] -> [DM, DIN]
        transpose_k<<<dim3((DM + 31) / 32, (DIN + 31) / 32), tb>>>(proj_in_w, p_wpi, DIN, DM);
        // proj_out_w: [DM, DIN] -> [DIN, DM]
        transpose_k<<<dim3((DIN + 31) / 32, (DM + 31) / 32), tb>>>(proj_out_w, p_wpo, DM, DIN);
        for (int i = 0; i < 4; i++) {
            // in_proj_w slice: [DM, DPJ] -> [DPJ, DM]
            transpose_k<<<dim3((DPJ + 31) / 32, (DM + 31) / 32), tb>>>(
                in_proj_w + (size_t)i * DM * DPJ, p_wti + (size_t)i * DPJ * DM, DM, DPJ);
            // out_proj_w slice: [DI, DM] -> [DM, DI]
            transpose_k<<<dim3((DM + 31) / 32, (DI + 31) / 32), tb>>>(
                out_proj_w + (size_t)i * DI * DM, p_wto + (size_t)i * DM * DI, DI, DM);
        }
    }

    // h = x @ proj_in_w + b ; apply mask token
    tgemm_k<<<dim3(DM / 128, BT / 128), 256, TG_SMEM>>>(x, p_wpi, proj_in_b, p_h, DM, DIN);
    mask_apply_k<<<BT, DM>>>(maskp, mask_token);

    for (int l = 0; l < 2; l++) {
        layernorm_k<<<BT, 256>>>(p_h, ln_w + l * DM, ln_b + l * DM, p_hn);
        for (int d = 0; d < 2; d++) {
            tgemm_k<<<dim3((DPJ + 127) / 128, BT / 128), 256, TG_SMEM>>>(
                p_hn,
                p_wti + (size_t)(l * 2 + d) * DPJ * DM,
                in_proj_b + (size_t)(l * 2 + d) * DPJ,
                p_zx + (size_t)d * BT * DPJ, DPJ, DM);
        }
        conv_silu_k<<<dim3((BT * CD + 255) / 256, 2), 256>>>(conv_w, conv_b, l);
        dt_prep_k<<<dim3(BT * NH / 256, 2), 256>>>(dt_bias, A_log, l);
        scan_k<<<dim3(Bb * NH, 2), HD>>>(Dp, l);
        gated_rms_k<<<dim3(BT, 2), 256>>>(ssm_w, l);
        for (int d = 0; d < 2; d++) {
            tgemm_k<<<dim3(DM / 128, BT / 128), 256, TG_SMEM>>>(
                p_yn + (size_t)d * BT * DI,
                p_wto + (size_t)(l * 2 + d) * DM * DI,
                nullptr,
                p_o + (size_t)d * BT * DM, DM, DI);
        }
        add3_k<<<BT * DM / 256, 256>>>();
    }

    // hidden = layernorm(h, final) -> g_hn ; outputs
    layernorm_k<<<BT, 256>>>(p_h, fn_w, fn_b, p_hn);

    const int PRED = BT * DIN, HID = BT * DM;
    float* predp = nullptr;
    float* hidp  = nullptr;
    if (out_size >= PRED + HID)      { predp = out; hidp = out + PRED; }
    else if (out_size == PRED)       { predp = out; }
    else                             { hidp = out; }

    if (hidp)
        copy_k<<<(HID + 255) / 256, 256>>>(p_hn, hidp, HID);
    if (predp)
        tgemm_k<<<dim3((DIN + 127) / 128, BT / 128), 256, TG_SMEM>>>(
            p_hn, p_wpo, proj_out_b, predp, DIN, DM);
}

// round 4
// speedup vs baseline: 1.7315x; 1.0542x over previous
#include <cuda_runtime.h>
#include <cuda_bf16.h>
#include <math.h>
#include <stdint.h>

#define Bb   4
#define Tt   1024
#define BT   4096          // Bb*Tt tokens
#define DM   768
#define DI   1536
#define NH   24
#define HD   64
#define DS   16
#define CD   1568          // D_INNER + 2*D_STATE
#define DPJ  3128          // 2*DI + 2*DS + NH
#define DIN  80
#define LEPS 1e-5f

// ---------------- scratch (device globals; no allocations allowed) ----------
__device__ float g_h [BT*DM];
__device__ float g_hn[BT*DM];
__device__ float g_zx [2][BT*DPJ];
__device__ float g_xbc[2][BT*CD];
__device__ float g_dt [2][BT*NH];
__device__ float g_dA [2][BT*NH];
__device__ float g_y  [2][BT*DI];
__device__ float g_yn [2][BT*DI];
__device__ float g_o  [2][BT*DM];
__device__ int   g_mask_kind;   // 0=int32, 1=float32, 2=uint8/bool
// bf16 hi/lo planes: weights transposed to [N,K]
__device__ __nv_bfloat16 g_wih[4][DPJ*DM], g_wil[4][DPJ*DM];
__device__ __nv_bfloat16 g_woh[4][DM*DI],  g_wol[4][DM*DI];
__device__ __nv_bfloat16 g_wpih[DM*DIN],   g_wpil[DM*DIN];
__device__ __nv_bfloat16 g_wpoh[DIN*DM],   g_wpol[DIN*DM];
// activation planes (reused)
__device__ __nv_bfloat16 g_ah[2][BT*DI],   g_al[2][BT*DI];

// ---------------- generic helpers ----------------
__device__ __forceinline__ float block_sum(float v, float* sh) {
    int lane = threadIdx.x & 31, wid = threadIdx.x >> 5;
    #pragma unroll
    for (int o = 16; o > 0; o >>= 1) v += __shfl_xor_sync(0xffffffffu, v, o);
    if (lane == 0) sh[wid] = v;
    __syncthreads();
    int nw = (blockDim.x + 31) >> 5;
    if (threadIdx.x < 32) {
        float t = (threadIdx.x < nw) ? sh[threadIdx.x] : 0.f;
        #pragma unroll
        for (int o = 16; o > 0; o >>= 1) t += __shfl_xor_sync(0xffffffffu, t, o);
        if (threadIdx.x == 0) sh[0] = t;
    }
    __syncthreads();
    float r = sh[0];
    __syncthreads();
    return r;
}

__device__ __forceinline__ float rsqrt_acc(float a) {
    float r = rsqrtf(a);
    r = r * (1.5f - 0.5f * a * r * r);
    return r;
}

__device__ __forceinline__ float silu_f(float v) {
    return v / (1.f + expf(-v));
}

__device__ __forceinline__ uint32_t smem_u32(const void* p) {
    uint32_t a;
    asm("{ .reg .u64 t; cvta.to.shared.u64 t, %1; cvt.u32.u64 %0, t; }" : "=r"(a) : "l"(p));
    return a;
}

// ---------------- tensor-core GEMM (bf16x3, cp.async + ldmatrix) ------------
// C[M,N] = Ah@Bh^T + Ah@Bl^T + Al@Bh^T + bias.
// A planes [M,K] bf16, B planes [N,K] bf16. M multiple of 128. K multiple of 8.
// CTA 128x128, 256 threads (8 warps 2x4), warp tile 64x32, K staged 32-wide.

#define SAS   40                // bf16 row stride in smem (80 bytes)
#define PLB   10240             // bytes per plane: 128*40*2
#define BUFB  (4*PLB)           // 40960 bytes per buffer
#define TG_SMEM (2*BUFB)        // 81920

#define MMA16816(acc, a, b) \
    asm volatile("mma.sync.aligned.m16n8k16.row.col.f32.bf16.bf16.f32 " \
        "{%0,%1,%2,%3},{%4,%5,%6,%7},{%8,%9},{%0,%1,%2,%3};" \
        : "+f"((acc)[0]), "+f"((acc)[1]), "+f"((acc)[2]), "+f"((acc)[3]) \
        : "r"((a)[0]), "r"((a)[1]), "r"((a)[2]), "r"((a)[3]), \
          "r"((b)[0]), "r"((b)[1]))

#define LDSM4(r, addr) \
    asm volatile("ldmatrix.sync.aligned.m8n8.x4.shared.b16 {%0,%1,%2,%3}, [%4];" \
        : "=r"((r)[0]), "=r"((r)[1]), "=r"((r)[2]), "=r"((r)[3]) : "r"(addr))

__device__ __forceinline__ void cpa16(uint32_t s, const void* g, int szr) {
    asm volatile("cp.async.cg.shared.global [%0], [%1], 16, %2;"
                 :: "r"(s), "l"(__cvta_generic_to_global(g)), "r"(szr) : "memory");
}

__global__ __launch_bounds__(256, 2)
void tgemm_k(const __nv_bfloat16* __restrict__ Ah, const __nv_bfloat16* __restrict__ Al,
             const __nv_bfloat16* __restrict__ Bh, const __nv_bfloat16* __restrict__ Bl,
             const float* __restrict__ bias, float* __restrict__ C,
             int N, int K) {
    extern __shared__ __align__(16) char smraw[];
    const uint32_t sb = smem_u32(smraw);
    const int tid  = threadIdx.x;
    const int lane = tid & 31, warp = tid >> 5;
    const int wr = warp >> 2, wc = warp & 3;
    const int gid = lane >> 2, tq = lane & 3;
    const int row0 = blockIdx.y * 128, n0 = blockIdx.x * 128;

    const int rw = lane & 7;
    const uint32_t aoff = (uint32_t)(((rw + ((lane >> 3) & 1) * 8) * SAS + (lane >> 4) * 8) * 2);
    const uint32_t boff = (uint32_t)(((rw + (lane >> 4) * 8) * SAS + ((lane >> 3) & 1) * 8) * 2);

    float acc[4][4][4];
    #pragma unroll
    for (int mi = 0; mi < 4; mi++)
        #pragma unroll
        for (int ni = 0; ni < 4; ni++)
            #pragma unroll
            for (int e = 0; e < 4; e++) acc[mi][ni][e] = 0.f;

    const int nst = (K + 31) >> 5;

    auto issue = [&](int s, int buf) {
        const int k0 = s * 32;
        const uint32_t base = sb + buf * BUFB;
        #pragma unroll
        for (int i = 0; i < 8; i++) {
            int task = i * 256 + tid;
            int plane = task >> 9;
            int idx = task & 511;
            int r = idx >> 2, c16 = idx & 3;
            uint32_t dst = base + plane * PLB + (uint32_t)((r * SAS + c16 * 8) * 2);
            int k = k0 + c16 * 8;
            const __nv_bfloat16* g;
            int sz = 16;
            if (plane < 2) {
                g = (plane ? Al : Ah) + (size_t)(row0 + r) * K + k;
                if (k + 8 > K) sz = 0;
            } else {
                int n = n0 + r;
                g = (plane == 3 ? Bl : Bh) + (size_t)n * K + k;
                if (k + 8 > K || n >= N) sz = 0;
            }
            if (sz == 0) g = Ah;
            cpa16(dst, g, sz);
        }
        asm volatile("cp.async.commit_group;" ::: "memory");
    };

    auto compute = [&](int buf) {
        const uint32_t sA = sb + buf * BUFB;
        const uint32_t sB = sA + 2 * PLB;
        #pragma unroll
        for (int kk = 0; kk < 32; kk += 16) {
            uint32_t ah[4][4], al[4][4];
            #pragma unroll
            for (int mi = 0; mi < 4; mi++) {
                uint32_t ab = sA + (uint32_t)(((wr * 64 + mi * 16) * SAS + kk) * 2);
                LDSM4(ah[mi], ab + aoff);
                LDSM4(al[mi], ab + PLB + aoff);
            }
            #pragma unroll
            for (int pr = 0; pr < 2; pr++) {
                uint32_t bh2[4], bl2[4];
                uint32_t bb = sB + (uint32_t)(((wc * 32 + pr * 16) * SAS + kk) * 2);
                LDSM4(bh2, bb + boff);
                LDSM4(bl2, bb + PLB + boff);
                #pragma unroll
                for (int q = 0; q < 2; q++) {
                    int ni = pr * 2 + q;
                    #pragma unroll
                    for (int mi = 0; mi < 4; mi++) {
                        MMA16816(acc[mi][ni], ah[mi], &bh2[q * 2]);
                        MMA16816(acc[mi][ni], ah[mi], &bl2[q * 2]);
                        MMA16816(acc[mi][ni], al[mi], &bh2[q * 2]);
                    }
                }
            }
        }
    };

    issue(0, 0);
    for (int s = 0; s < nst; s++) {
        if (s + 1 < nst) {
            issue(s + 1, (s + 1) & 1);
            asm volatile("cp.async.wait_group 1;" ::: "memory");
        } else {
            asm volatile("cp.async.wait_group 0;" ::: "memory");
        }
        __syncthreads();
        compute(s & 1);
        __syncthreads();
    }

    // epilogue: fragments + bias -> global
    #pragma unroll
    for (int mi = 0; mi < 4; mi++) {
        int row = row0 + wr * 64 + mi * 16 + gid;
        #pragma unroll
        for (int ni = 0; ni < 4; ni++) {
            int col = n0 + wc * 32 + ni * 8 + tq * 2;
            if (col < N) {
                float b0 = bias ? bias[col]     : 0.f;
                float b1 = bias ? bias[col + 1] : 0.f;
                float* c0 = C + (size_t)row * N + col;
                c0[0] = acc[mi][ni][0] + b0;
                c0[1] = acc[mi][ni][1] + b1;
                float* c1 = C + (size_t)(row + 8) * N + col;
                c1[0] = acc[mi][ni][2] + b0;
                c1[1] = acc[mi][ni][3] + b1;
            }
        }
    }
}

// ---------------- weight convert+transpose: src[R,C] fp32 -> dst[C,R] hi/lo -
__global__ void convert_wt_k(const float* __restrict__ src,
                             __nv_bfloat16* __restrict__ dhi,
                             __nv_bfloat16* __restrict__ dlo,
                             int R, int C) {
    __shared__ float tile[32][33];
    int c0 = blockIdx.x * 32, r0 = blockIdx.y * 32;
    int x = c0 + threadIdx.x;
    #pragma unroll
    for (int j = threadIdx.y; j < 32; j += 8) {
        int r = r0 + j;
        tile[j][threadIdx.x] = (r < R && x < C) ? src[(size_t)r * C + x] : 0.f;
    }
    __syncthreads();
    int xr = r0 + threadIdx.x;
    #pragma unroll
    for (int j = threadIdx.y; j < 32; j += 8) {
        int c = c0 + j;
        if (c < C && xr < R) {
            float v = tile[threadIdx.x][j];
            __nv_bfloat16 h = __float2bfloat16_rn(v);
            __nv_bfloat16 l = __float2bfloat16_rn(v - __bfloat162float(h));
            dhi[(size_t)c * R + xr] = h;
            dlo[(size_t)c * R + xr] = l;
        }
    }
}

// ---------------- activation convert: fp32 -> bf16 hi/lo --------------------
__global__ void convert_a_k(const float* __restrict__ src,
                            __nv_bfloat16* __restrict__ dhi,
                            __nv_bfloat16* __restrict__ dlo, int n) {
    int i = blockIdx.x * 256 + threadIdx.x;
    if (i < n) {
        float v = src[i];
        __nv_bfloat16 h = __float2bfloat16_rn(v);
        __nv_bfloat16 l = __float2bfloat16_rn(v - __bfloat162float(h));
        dhi[i] = h;
        dlo[i] = l;
    }
}

// ---------------- mask dtype detector -----------
__global__ void detect_mask_k(const unsigned int* __restrict__ m) {
    __shared__ int s_ni, s_nf;
    if (threadIdx.x == 0) { s_ni = 0; s_nf = 0; }
    __syncthreads();
    int ni = 0, nf = 0;
    for (int i = threadIdx.x; i < 1024; i += blockDim.x) {
        unsigned w = m[i];
        if (w != 0u && w != 1u)           ni = 1;
        if (w != 0u && w != 0x3F800000u)  nf = 1;
    }
    if (ni) atomicOr(&s_ni, 1);
    if (nf) atomicOr(&s_nf, 1);
    __syncthreads();
    if (threadIdx.x == 0)
        g_mask_kind = (!s_ni) ? 0 : ((!s_nf) ? 1 : 2);
}

__global__ void mask_apply_k(const void* __restrict__ maskp,
                             const float* __restrict__ mask_token) {
    int bt = blockIdx.x;
    int kind = g_mask_kind;
    bool is;
    if (kind == 0)      is = ((const int*)maskp)[bt] != 0;
    else if (kind == 1) is = ((const float*)maskp)[bt] != 0.f;
    else                is = ((const unsigned char*)maskp)[bt] != 0;
    if (is) g_h[bt * DM + threadIdx.x] = mask_token[threadIdx.x];
}

// ---------------- LayerNorm over 768, one block per token -------------------
__global__ void layernorm_k(const float* __restrict__ in, const float* __restrict__ w,
                            const float* __restrict__ b, float* __restrict__ out) {
    __shared__ float sh[32];
    int row = blockIdx.x;
    const float* x = in + (size_t)row * DM;
    int t = threadIdx.x;
    float v0 = x[t], v1 = x[t + 256], v2 = x[t + 512];
    float S  = block_sum(v0 + v1 + v2, sh);
    float mu = S * (1.f / DM);
    float d0 = v0 - mu, d1 = v1 - mu, d2 = v2 - mu;
    float S2 = block_sum(d0 * d0 + d1 * d1 + d2 * d2, sh);
    float inv = rsqrt_acc(S2 * (1.f / DM) + LEPS);
    float* o = out + (size_t)row * DM;
    o[t]       = d0 * inv * w[t]       + b[t];
    o[t + 256] = d1 * inv * w[t + 256] + b[t + 256];
    o[t + 512] = d2 * inv * w[t + 512] + b[t + 512];
}

// ---------------- depthwise causal conv7 + silu (both dirs) -----------------
__global__ void conv_silu_k(const float* __restrict__ cw, const float* __restrict__ cb, int l) {
    int d = blockIdx.y;
    int idx = blockIdx.x * 256 + threadIdx.x;
    if (idx >= BT * CD) return;
    int c = idx % CD;
    int btt = idx / CD;
    int b = btt >> 10, t = btt & 1023;
    const float* w = cw + ((size_t)(l * 2 + d) * CD + c) * 7;
    float acc = cb[(l * 2 + d) * CD + c];
    const float* src = g_zx[d];
    if (d == 0) {
        #pragma unroll
        for (int k = 0; k < 7; k++) {
            int tt = t - 6 + k;
            if (tt >= 0) acc = fmaf(w[k], src[(size_t)(b * Tt + tt) * DPJ + 1536 + c], acc);
        }
    } else {
        #pragma unroll
        for (int k = 0; k < 7; k++) {
            int tt = t + 6 - k;
            if (tt < Tt) acc = fmaf(w[k], src[(size_t)(b * Tt + tt) * DPJ + 1536 + c], acc);
        }
    }
    g_xbc[d][idx] = silu_f(acc);
}

// ---------------- dt: softplus + dA ------------------------------------------
__global__ void dt_prep_k(const float* __restrict__ dt_bias, const float* __restrict__ A_log, int l) {
    int d = blockIdx.y;
    int idx = blockIdx.x * 256 + threadIdx.x;
    int h = idx % NH;
    int bt = idx / NH;
    float raw = g_zx[d][(size_t)bt * DPJ + 3104 + h] + dt_bias[(l * 2 + d) * NH + h];
    float dt = (raw > 20.f) ? raw : log1pf(expf(raw));
    float a = -expf(A_log[(l * 2 + d) * NH + h]);
    g_dt[d][idx] = dt;
    g_dA[d][idx] = expf(a * dt);
}

// ---------------- sequential SSM scan: one block per (b, head, dir) ---------
__global__ void scan_k(const float* __restrict__ Dp, int l) {
    const int d  = blockIdx.y;
    const int bh = blockIdx.x;
    const int b  = bh / NH, hh = bh % NH;
    const int p  = threadIdx.x;
    const float* __restrict__ xbc = g_xbc[d];
    const float* __restrict__ dtp = g_dt[d];
    const float* __restrict__ dAp = g_dA[d];
    float* __restrict__ yb = g_y[d];
    const float Dc = Dp[(l * 2 + d) * NH + hh];
    float s[16];
    #pragma unroll
    for (int n = 0; n < 16; n++) s[n] = 0.f;
    for (int i = 0; i < Tt; i++) {
        int t  = d ? (Tt - 1 - i) : i;
        int bt = b * Tt + t;
        const float* row = xbc + (size_t)bt * CD;
        float x  = row[hh * HD + p];
        float dt = dtp[bt * NH + hh];
        float dA = dAp[bt * NH + hh];
        float Bv[16], Cv[16];
        #pragma unroll
        for (int q = 0; q < 4; q++) {
            *(float4*)&Bv[q * 4] = *(const float4*)(row + 1536 + q * 4);
            *(float4*)&Cv[q * 4] = *(const float4*)(row + 1552 + q * 4);
        }
        float c0 = dt * x;
        float a0 = 0.f, a1 = 0.f, a2 = 0.f, a3 = 0.f;
        #pragma unroll
        for (int n = 0; n < 16; n += 4) {
            s[n + 0] = fmaf(s[n + 0], dA, c0 * Bv[n + 0]); a0 = fmaf(s[n + 0], Cv[n + 0], a0);
            s[n + 1] = fmaf(s[n + 1], dA, c0 * Bv[n + 1]); a1 = fmaf(s[n + 1], Cv[n + 1], a1);
            s[n + 2] = fmaf(s[n + 2], dA, c0 * Bv[n + 2]); a2 = fmaf(s[n + 2], Cv[n + 2], a2);
            s[n + 3] = fmaf(s[n + 3], dA, c0 * Bv[n + 3]); a3 = fmaf(s[n + 3], Cv[n + 3], a3);
        }
        yb[(size_t)bt * DI + hh * HD + p] = (a0 + a1) + (a2 + a3) + Dc * x;
    }
}

// ---------------- gated RMS norm over 1536 ----------------------------------
__global__ void gated_rms_k(const float* __restrict__ ssm_w, int l) {
    __shared__ float sh[32];
    int d = blockIdx.y;
    int row = blockIdx.x;
    const float* y = g_y[d] + (size_t)row * DI;
    const float* z = g_zx[d] + (size_t)row * DPJ;
    float* out = g_yn[d] + (size_t)row * DI;
    const float* w = ssm_w + (l * 2 + d) * DI;
    int t = threadIdx.x;
    float g[6], s2 = 0.f;
    #pragma unroll
    for (int i = 0; i < 6; i++) {
        int c = t + 256 * i;
        float gv = y[c] * silu_f(z[c]);
        g[i] = gv;
        s2 += gv * gv;
    }
    float S2 = block_sum(s2, sh);
    float inv = rsqrt_acc(S2 * (1.f / DI) + LEPS);
    #pragma unroll
    for (int i = 0; i < 6; i++) {
        int c = t + 256 * i;
        out[c] = g[i] * inv * w[c];
    }
}

// ---------------- residual add: h += o0 + o1 --------------------------------
__global__ void add3_k() {
    int i = blockIdx.x * 256 + threadIdx.x;
    g_h[i] += g_o[0][i] + g_o[1][i];
}

__global__ void copy_k(const float* __restrict__ src, float* __restrict__ dst, int n) {
    int i = blockIdx.x * 256 + threadIdx.x;
    if (i < n) dst[i] = src[i];
}

// ---------------- launcher ---------------------------------------------------
extern "C" void kernel_launch(void* const* d_in, const int* in_sizes, int n_in,
                              void* d_out, int out_size) {
    const float* x          = (const float*)d_in[0];
    const void*  maskp      = d_in[1];
    const float* proj_in_w  = (const float*)d_in[2];
    const float* proj_in_b  = (const float*)d_in[3];
    const float* mask_token = (const float*)d_in[4];
    const float* ln_w       = (const float*)d_in[5];
    const float* ln_b       = (const float*)d_in[6];
    const float* in_proj_w  = (const float*)d_in[7];
    const float* in_proj_b  = (const float*)d_in[8];
    const float* conv_w     = (const float*)d_in[9];
    const float* conv_b     = (const float*)d_in[10];
    const float* dt_bias    = (const float*)d_in[11];
    const float* A_log      = (const float*)d_in[12];
    const float* Dp         = (const float*)d_in[13];
    const float* ssm_w      = (const float*)d_in[14];
    const float* out_proj_w = (const float*)d_in[15];
    const float* fn_w       = (const float*)d_in[16];
    const float* fn_b       = (const float*)d_in[17];
    const float* proj_out_w = (const float*)d_in[18];
    const float* proj_out_b = (const float*)d_in[19];
    float* out = (float*)d_out;

    float *p_h, *p_hn, *p_zx, *p_yn, *p_o;
    __nv_bfloat16 *p_wih, *p_wil, *p_woh, *p_wol, *p_wpih, *p_wpil, *p_wpoh, *p_wpol;
    __nv_bfloat16 *p_ah, *p_al;
    cudaGetSymbolAddress((void**)&p_h,    g_h);
    cudaGetSymbolAddress((void**)&p_hn,   g_hn);
    cudaGetSymbolAddress((void**)&p_zx,   g_zx);
    cudaGetSymbolAddress((void**)&p_yn,   g_yn);
    cudaGetSymbolAddress((void**)&p_o,    g_o);
    cudaGetSymbolAddress((void**)&p_wih,  g_wih);
    cudaGetSymbolAddress((void**)&p_wil,  g_wil);
    cudaGetSymbolAddress((void**)&p_woh,  g_woh);
    cudaGetSymbolAddress((void**)&p_wol,  g_wol);
    cudaGetSymbolAddress((void**)&p_wpih, g_wpih);
    cudaGetSymbolAddress((void**)&p_wpil, g_wpil);
    cudaGetSymbolAddress((void**)&p_wpoh, g_wpoh);
    cudaGetSymbolAddress((void**)&p_wpol, g_wpol);
    cudaGetSymbolAddress((void**)&p_ah,   g_ah);
    cudaGetSymbolAddress((void**)&p_al,   g_al);

    cudaFuncSetAttribute(tgemm_k, cudaFuncAttributeMaxDynamicSharedMemorySize, TG_SMEM);

    detect_mask_k<<<1, 256>>>((const unsigned int*)maskp);

    // weight conversions (transpose + bf16 hi/lo split)
    {
        dim3 tb(32, 8);
        convert_wt_k<<<dim3((DM + 31) / 32, (DIN + 31) / 32), tb>>>(proj_in_w, p_wpih, p_wpil, DIN, DM);
        convert_wt_k<<<dim3((DIN + 31) / 32, (DM + 31) / 32), tb>>>(proj_out_w, p_wpoh, p_wpol, DM, DIN);
        for (int i = 0; i < 4; i++) {
            convert_wt_k<<<dim3((DPJ + 31) / 32, (DM + 31) / 32), tb>>>(
                in_proj_w + (size_t)i * DM * DPJ,
                p_wih + (size_t)i * DPJ * DM, p_wil + (size_t)i * DPJ * DM, DM, DPJ);
            convert_wt_k<<<dim3((DM + 31) / 32, (DI + 31) / 32), tb>>>(
                out_proj_w + (size_t)i * DI * DM,
                p_woh + (size_t)i * DM * DI, p_wol + (size_t)i * DM * DI, DI, DM);
        }
    }

    // h = x @ proj_in_w + b ; apply mask token
    convert_a_k<<<(BT * DIN + 255) / 256, 256>>>(x, p_ah, p_al, BT * DIN);
    tgemm_k<<<dim3(DM / 128, BT / 128), 256, TG_SMEM>>>(
        p_ah, p_al, p_wpih, p_wpil, proj_in_b, p_h, DM, DIN);
    mask_apply_k<<<BT, DM>>>(maskp, mask_token);

    for (int l = 0; l < 2; l++) {
        layernorm_k<<<BT, 256>>>(p_h, ln_w + l * DM, ln_b + l * DM, p_hn);
        convert_a_k<<<(BT * DM + 255) / 256, 256>>>(p_hn, p_ah, p_al, BT * DM);
        for (int d = 0; d < 2; d++) {
            tgemm_k<<<dim3((DPJ + 127) / 128, BT / 128), 256, TG_SMEM>>>(
                p_ah, p_al,
                p_wih + (size_t)(l * 2 + d) * DPJ * DM,
                p_wil + (size_t)(l * 2 + d) * DPJ * DM,
                in_proj_b + (size_t)(l * 2 + d) * DPJ,
                p_zx + (size_t)d * BT * DPJ, DPJ, DM);
        }
        conv_silu_k<<<dim3((BT * CD + 255) / 256, 2), 256>>>(conv_w, conv_b, l);
        dt_prep_k<<<dim3(BT * NH / 256, 2), 256>>>(dt_bias, A_log, l);
        scan_k<<<dim3(Bb * NH, 2), HD>>>(Dp, l);
        gated_rms_k<<<dim3(BT, 2), 256>>>(ssm_w, l);
        for (int d = 0; d < 2; d++) {
            convert_a_k<<<(BT * DI + 255) / 256, 256>>>(
                p_yn + (size_t)d * BT * DI,
                p_ah + (size_t)d * BT * DI, p_al + (size_t)d * BT * DI, BT * DI);
            tgemm_k<<<dim3(DM / 128, BT / 128), 256, TG_SMEM>>>(
                p_ah + (size_t)d * BT * DI, p_al + (size_t)d * BT * DI,
                p_woh + (size_t)(l * 2 + d) * DM * DI,
                p_wol + (size_t)(l * 2 + d) * DM * DI,
                nullptr,
                p_o + (size_t)d * BT * DM, DM, DI);
        }
        add3_k<<<BT * DM / 256, 256>>>();
    }

    // hidden = layernorm(h, final) -> g_hn ; outputs
    layernorm_k<<<BT, 256>>>(p_h, fn_w, fn_b, p_hn);

    const int PRED = BT * DIN, HID = BT * DM;
    float* predp = nullptr;
    float* hidp  = nullptr;
    if (out_size >= PRED + HID)      { predp = out; hidp = out + PRED; }
    else if (out_size == PRED)       { predp = out; }
    else                             { hidp = out; }

    if (hidp)
        copy_k<<<(HID + 255) / 256, 256>>>(p_hn, hidp, HID);
    if (predp) {
        convert_a_k<<<(BT * DM + 255) / 256, 256>>>(p_hn, p_ah, p_al, BT * DM);
        tgemm_k<<<dim3((DIN + 127) / 128, BT / 128), 256, TG_SMEM>>>(
            p_ah, p_al, p_wpoh, p_wpol, proj_out_b, predp, DIN, DM);
    }
}

// round 5
// speedup vs baseline: 2.3504x; 1.3575x over previous
#include <cuda_runtime.h>
#include <cuda_fp16.h>
#include <math.h>
#include <stdint.h>

#define Bb   4
#define Tt   1024
#define BT   4096          // Bb*Tt tokens
#define DM   768
#define DI   1536
#define NH   24
#define HD   64
#define DS   16
#define CD   1568          // D_INNER + 2*D_STATE
#define DPJ  3128          // 2*DI + 2*DS + NH
#define DIN  80
#define LEPS 1e-5f

// ---------------- scratch (device globals; no allocations allowed) ----------
__device__ float g_h  [BT*DM];
__device__ float g_hn [BT*DM];
__device__ float g_zx [2][BT*DPJ];
__device__ float g_xbc[2][BT*CD];
__device__ float g_dt [2][BT*NH];
__device__ float g_dA [2][BT*NH];
__device__ float g_y  [2][BT*DI];
__device__ float g_o  [2][BT*DM];
__device__ int   g_mask_kind;   // 0=int32, 1=float32, 2=uint8/bool
// fp16 weight planes, transposed to [N,K]
__device__ __half g_wih[4][DPJ*DM], g_wil[4][DPJ*DM];
__device__ __half g_woh[4][DM*DI],  g_wol[4][DM*DI];
__device__ __half g_wpih[DM*DIN],   g_wpil[DM*DIN];
__device__ __half g_wpoh[DIN*DM],   g_wpol[DIN*DM];
// fp16 activation planes
__device__ __half g_hn16[BT*DM];
__device__ __half g_yn16[2][BT*DI];
__device__ __half g_x16 [BT*DIN];

// ---------------- generic helpers ----------------
__device__ __forceinline__ float block_sum(float v, float* sh) {
    int lane = threadIdx.x & 31, wid = threadIdx.x >> 5;
    #pragma unroll
    for (int o = 16; o > 0; o >>= 1) v += __shfl_xor_sync(0xffffffffu, v, o);
    if (lane == 0) sh[wid] = v;
    __syncthreads();
    int nw = (blockDim.x + 31) >> 5;
    if (threadIdx.x < 32) {
        float t = (threadIdx.x < nw) ? sh[threadIdx.x] : 0.f;
        #pragma unroll
        for (int o = 16; o > 0; o >>= 1) t += __shfl_xor_sync(0xffffffffu, t, o);
        if (threadIdx.x == 0) sh[0] = t;
    }
    __syncthreads();
    float r = sh[0];
    __syncthreads();
    return r;
}

__device__ __forceinline__ float rsqrt_acc(float a) {
    float r = rsqrtf(a);
    r = r * (1.5f - 0.5f * a * r * r);
    return r;
}

__device__ __forceinline__ float silu_f(float v) {
    return v / (1.f + expf(-v));
}

__device__ __forceinline__ uint32_t smem_u32(const void* p) {
    uint32_t a;
    asm("{ .reg .u64 t; cvta.to.shared.u64 t, %1; cvt.u32.u64 %0, t; }" : "=r"(a) : "l"(p));
    return a;
}

// ---------------- tensor-core GEMM (fp16 x2: A16 @ (Wh+Wl)^T) ---------------
// C[M,N] = A16[M,K] @ (Wh+Wl)[N,K]^T + bias. M mult of 128, K mult of 8.
// CTA 128x128, 256 threads (8 warps 2x4), warp tile 64x32, K staged 32-wide.

#define SAS   40                // half row stride in smem (80 bytes)
#define PLB   10240             // bytes per plane: 128*40*2
#define BUFB  (3*PLB)           // A, Wh, Wl = 30720 bytes per buffer
#define TG_SMEM (2*BUFB)        // 61440

#define MMA16816(acc, a, b) \
    asm volatile("mma.sync.aligned.m16n8k16.row.col.f32.f16.f16.f32 " \
        "{%0,%1,%2,%3},{%4,%5,%6,%7},{%8,%9},{%0,%1,%2,%3};" \
        : "+f"((acc)[0]), "+f"((acc)[1]), "+f"((acc)[2]), "+f"((acc)[3]) \
        : "r"((a)[0]), "r"((a)[1]), "r"((a)[2]), "r"((a)[3]), \
          "r"((b)[0]), "r"((b)[1]))

#define LDSM4(r, addr) \
    asm volatile("ldmatrix.sync.aligned.m8n8.x4.shared.b16 {%0,%1,%2,%3}, [%4];" \
        : "=r"((r)[0]), "=r"((r)[1]), "=r"((r)[2]), "=r"((r)[3]) : "r"(addr))

__device__ __forceinline__ void cpa16(uint32_t s, const void* g, int szr) {
    asm volatile("cp.async.cg.shared.global [%0], [%1], 16, %2;"
                 :: "r"(s), "l"(__cvta_generic_to_global(g)), "r"(szr) : "memory");
}

__global__ __launch_bounds__(256, 2)
void tgemm_k(const __half* __restrict__ A16,
             const __half* __restrict__ Wh, const __half* __restrict__ Wl,
             const float* __restrict__ bias, float* __restrict__ C,
             int N, int K) {
    extern __shared__ __align__(16) char smraw[];
    const uint32_t sb = smem_u32(smraw);
    const int tid  = threadIdx.x;
    const int lane = tid & 31, warp = tid >> 5;
    const int wr = warp >> 2, wc = warp & 3;
    const int gid = lane >> 2, tq = lane & 3;
    const int row0 = blockIdx.y * 128, n0 = blockIdx.x * 128;

    const int rw = lane & 7;
    const uint32_t aoff = (uint32_t)(((rw + ((lane >> 3) & 1) * 8) * SAS + (lane >> 4) * 8) * 2);
    const uint32_t boff = (uint32_t)(((rw + (lane >> 4) * 8) * SAS + ((lane >> 3) & 1) * 8) * 2);

    float acc[4][4][4];
    #pragma unroll
    for (int mi = 0; mi < 4; mi++)
        #pragma unroll
        for (int ni = 0; ni < 4; ni++)
            #pragma unroll
            for (int e = 0; e < 4; e++) acc[mi][ni][e] = 0.f;

    const int nst = (K + 31) >> 5;

    auto issue = [&](int s, int buf) {
        const int k0 = s * 32;
        const uint32_t base = sb + buf * BUFB;
        #pragma unroll
        for (int i = 0; i < 6; i++) {
            int task = i * 256 + tid;          // 0..1535
            int plane = task >> 9;             // 0:A 1:Wh 2:Wl
            int idx = task & 511;
            int r = idx >> 2, c16 = idx & 3;
            uint32_t dst = base + plane * PLB + (uint32_t)((r * SAS + c16 * 8) * 2);
            int k = k0 + c16 * 8;
            const __half* g;
            int sz = 16;
            if (plane == 0) {
                g = A16 + (size_t)(row0 + r) * K + k;
                if (k + 8 > K) sz = 0;
            } else {
                int n = n0 + r;
                g = (plane == 2 ? Wl : Wh) + (size_t)n * K + k;
                if (k + 8 > K || n >= N) sz = 0;
            }
            if (sz == 0) g = A16;
            cpa16(dst, g, sz);
        }
        asm volatile("cp.async.commit_group;" ::: "memory");
    };

    auto compute = [&](int buf) {
        const uint32_t sA = sb + buf * BUFB;
        const uint32_t sW = sA + PLB;
        #pragma unroll
        for (int kk = 0; kk < 32; kk += 16) {
            uint32_t ah[4][4];
            #pragma unroll
            for (int mi = 0; mi < 4; mi++) {
                uint32_t ab = sA + (uint32_t)(((wr * 64 + mi * 16) * SAS + kk) * 2);
                LDSM4(ah[mi], ab + aoff);
            }
            #pragma unroll
            for (int pr = 0; pr < 2; pr++) {
                uint32_t bh2[4], bl2[4];
                uint32_t bb = sW + (uint32_t)(((wc * 32 + pr * 16) * SAS + kk) * 2);
                LDSM4(bh2, bb + boff);
                LDSM4(bl2, bb + PLB + boff);
                #pragma unroll
                for (int q = 0; q < 2; q++) {
                    int ni = pr * 2 + q;
                    #pragma unroll
                    for (int mi = 0; mi < 4; mi++) {
                        MMA16816(acc[mi][ni], ah[mi], &bh2[q * 2]);
                        MMA16816(acc[mi][ni], ah[mi], &bl2[q * 2]);
                    }
                }
            }
        }
    };

    issue(0, 0);
    for (int s = 0; s < nst; s++) {
        if (s + 1 < nst) {
            issue(s + 1, (s + 1) & 1);
            asm volatile("cp.async.wait_group 1;" ::: "memory");
        } else {
            asm volatile("cp.async.wait_group 0;" ::: "memory");
        }
        __syncthreads();
        compute(s & 1);
        __syncthreads();
    }

    #pragma unroll
    for (int mi = 0; mi < 4; mi++) {
        int row = row0 + wr * 64 + mi * 16 + gid;
        #pragma unroll
        for (int ni = 0; ni < 4; ni++) {
            int col = n0 + wc * 32 + ni * 8 + tq * 2;
            if (col < N) {
                float b0 = bias ? bias[col]     : 0.f;
                float b1 = bias ? bias[col + 1] : 0.f;
                float* c0 = C + (size_t)row * N + col;
                c0[0] = acc[mi][ni][0] + b0;
                c0[1] = acc[mi][ni][1] + b1;
                float* c1 = C + (size_t)(row + 8) * N + col;
                c1[0] = acc[mi][ni][2] + b0;
                c1[1] = acc[mi][ni][3] + b1;
            }
        }
    }
}

// ---------------- weight convert+transpose: src[R,C] fp32 -> dst[C,R] hi/lo -
__global__ void convert_wt_k(const float* __restrict__ src,
                             __half* __restrict__ dhi, __half* __restrict__ dlo,
                             int R, int C) {
    __shared__ float tile[32][33];
    int c0 = blockIdx.x * 32, r0 = blockIdx.y * 32;
    int x = c0 + threadIdx.x;
    #pragma unroll
    for (int j = threadIdx.y; j < 32; j += 8) {
        int r = r0 + j;
        tile[j][threadIdx.x] = (r < R && x < C) ? src[(size_t)r * C + x] : 0.f;
    }
    __syncthreads();
    int xr = r0 + threadIdx.x;
    #pragma unroll
    for (int j = threadIdx.y; j < 32; j += 8) {
        int c = c0 + j;
        if (c < C && xr < R) {
            float v = tile[threadIdx.x][j];
            __half h = __float2half_rn(v);
            __half l = __float2half_rn(v - __half2float(h));
            dhi[(size_t)c * R + xr] = h;
            dlo[(size_t)c * R + xr] = l;
        }
    }
}

// ---------------- activation convert: fp32 -> fp16 --------------------------
__global__ void convert_a_k(const float* __restrict__ src,
                            __half* __restrict__ dst, int n) {
    int i = blockIdx.x * 256 + threadIdx.x;
    if (i < n) dst[i] = __float2half_rn(src[i]);
}

// ---------------- mask dtype detector -----------
__global__ void detect_mask_k(const unsigned int* __restrict__ m) {
    __shared__ int s_ni, s_nf;
    if (threadIdx.x == 0) { s_ni = 0; s_nf = 0; }
    __syncthreads();
    int ni = 0, nf = 0;
    for (int i = threadIdx.x; i < 1024; i += blockDim.x) {
        unsigned w = m[i];
        if (w != 0u && w != 1u)           ni = 1;
        if (w != 0u && w != 0x3F800000u)  nf = 1;
    }
    if (ni) atomicOr(&s_ni, 1);
    if (nf) atomicOr(&s_nf, 1);
    __syncthreads();
    if (threadIdx.x == 0)
        g_mask_kind = (!s_ni) ? 0 : ((!s_nf) ? 1 : 2);
}

__global__ void mask_apply_k(const void* __restrict__ maskp,
                             const float* __restrict__ mask_token) {
    int bt = blockIdx.x;
    int kind = g_mask_kind;
    bool is;
    if (kind == 0)      is = ((const int*)maskp)[bt] != 0;
    else if (kind == 1) is = ((const float*)maskp)[bt] != 0.f;
    else                is = ((const unsigned char*)maskp)[bt] != 0;
    if (is) g_h[bt * DM + threadIdx.x] = mask_token[threadIdx.x];
}

// ---------------- LayerNorm over 768; optional fp32 and fp16 outputs --------
__global__ void layernorm_k(const float* __restrict__ in, const float* __restrict__ w,
                            const float* __restrict__ b, float* __restrict__ out,
                            __half* __restrict__ out16) {
    __shared__ float sh[32];
    int row = blockIdx.x;
    const float* x = in + (size_t)row * DM;
    int t = threadIdx.x;
    float v0 = x[t], v1 = x[t + 256], v2 = x[t + 512];
    float S  = block_sum(v0 + v1 + v2, sh);
    float mu = S * (1.f / DM);
    float d0 = v0 - mu, d1 = v1 - mu, d2 = v2 - mu;
    float S2 = block_sum(d0 * d0 + d1 * d1 + d2 * d2, sh);
    float inv = rsqrt_acc(S2 * (1.f / DM) + LEPS);
    float r0 = d0 * inv * w[t]       + b[t];
    float r1 = d1 * inv * w[t + 256] + b[t + 256];
    float r2 = d2 * inv * w[t + 512] + b[t + 512];
    if (out) {
        float* o = out + (size_t)row * DM;
        o[t] = r0; o[t + 256] = r1; o[t + 512] = r2;
    }
    if (out16) {
        __half* o = out16 + (size_t)row * DM;
        o[t]       = __float2half_rn(r0);
        o[t + 256] = __float2half_rn(r1);
        o[t + 512] = __float2half_rn(r2);
    }
}

// ---------------- depthwise causal conv7 + silu (both dirs) -----------------
__global__ void conv_silu_k(const float* __restrict__ cw, const float* __restrict__ cb, int l) {
    int d = blockIdx.y;
    int idx = blockIdx.x * 256 + threadIdx.x;
    if (idx >= BT * CD) return;
    int c = idx % CD;
    int btt = idx / CD;
    int b = btt >> 10, t = btt & 1023;
    const float* w = cw + ((size_t)(l * 2 + d) * CD + c) * 7;
    float acc = cb[(l * 2 + d) * CD + c];
    const float* src = g_zx[d];
    if (d == 0) {
        #pragma unroll
        for (int k = 0; k < 7; k++) {
            int tt = t - 6 + k;
            if (tt >= 0) acc = fmaf(w[k], src[(size_t)(b * Tt + tt) * DPJ + 1536 + c], acc);
        }
    } else {
        #pragma unroll
        for (int k = 0; k < 7; k++) {
            int tt = t + 6 - k;
            if (tt < Tt) acc = fmaf(w[k], src[(size_t)(b * Tt + tt) * DPJ + 1536 + c], acc);
        }
    }
    g_xbc[d][idx] = silu_f(acc);
}

// ---------------- dt: softplus + dA ------------------------------------------
__global__ void dt_prep_k(const float* __restrict__ dt_bias, const float* __restrict__ A_log, int l) {
    int d = blockIdx.y;
    int idx = blockIdx.x * 256 + threadIdx.x;
    int h = idx % NH;
    int bt = idx / NH;
    float raw = g_zx[d][(size_t)bt * DPJ + 3104 + h] + dt_bias[(l * 2 + d) * NH + h];
    float dt = (raw > 20.f) ? raw : log1pf(expf(raw));
    float a = -expf(A_log[(l * 2 + d) * NH + h]);
    g_dt[d][idx] = dt;
    g_dA[d][idx] = expf(a * dt);
}

// ---------------- sequential SSM scan with register ping-pong prefetch ------
__global__ void scan_k(const float* __restrict__ Dp, int l) {
    const int d  = blockIdx.y;
    const int bh = blockIdx.x;
    const int b  = bh / NH, hh = bh % NH;
    const int p  = threadIdx.x;
    const float* __restrict__ xbc = g_xbc[d];
    const float* __restrict__ dtp = g_dt[d];
    const float* __restrict__ dAp = g_dA[d];
    float* __restrict__ yb = g_y[d];
    const float Dc = Dp[(l * 2 + d) * NH + hh];
    float s[16];
    #pragma unroll
    for (int n = 0; n < 16; n++) s[n] = 0.f;

    float xA, dtA, dAA, BA[16], CA[16];
    float xB, dtB, dAB, BB[16], CB[16];

    #define SCAN_LOAD(i, X, DT, DA, BV, CV) do {                              \
        int t_ = d ? (Tt - 1 - (i)) : (i);                                    \
        int bt_ = b * Tt + t_;                                                \
        const float* row_ = xbc + (size_t)bt_ * CD;                           \
        X  = row_[hh * HD + p];                                               \
        DT = dtp[bt_ * NH + hh];                                              \
        DA = dAp[bt_ * NH + hh];                                              \
        _Pragma("unroll")                                                     \
        for (int q = 0; q < 4; q++) {                                         \
            *(float4*)&BV[q * 4] = *(const float4*)(row_ + 1536 + q * 4);     \
            *(float4*)&CV[q * 4] = *(const float4*)(row_ + 1552 + q * 4);     \
        }                                                                     \
    } while (0)

    #define SCAN_COMP(i, X, DT, DA, BV, CV) do {                              \
        int t_ = d ? (Tt - 1 - (i)) : (i);                                    \
        int bt_ = b * Tt + t_;                                                \
        float c0_ = DT * X;                                                   \
        float a0 = 0.f, a1 = 0.f, a2 = 0.f, a3 = 0.f;                         \
        _Pragma("unroll")                                                     \
        for (int n = 0; n < 16; n += 4) {                                     \
            s[n+0] = fmaf(s[n+0], DA, c0_ * BV[n+0]); a0 = fmaf(s[n+0], CV[n+0], a0); \
            s[n+1] = fmaf(s[n+1], DA, c0_ * BV[n+1]); a1 = fmaf(s[n+1], CV[n+1], a1); \
            s[n+2] = fmaf(s[n+2], DA, c0_ * BV[n+2]); a2 = fmaf(s[n+2], CV[n+2], a2); \
            s[n+3] = fmaf(s[n+3], DA, c0_ * BV[n+3]); a3 = fmaf(s[n+3], CV[n+3], a3); \
        }                                                                     \
        yb[(size_t)bt_ * DI + hh * HD + p] = (a0 + a1) + (a2 + a3) + Dc * X;  \
    } while (0)

    SCAN_LOAD(0, xA, dtA, dAA, BA, CA);
    for (int i = 0; i < Tt; i += 2) {
        SCAN_LOAD(i + 1, xB, dtB, dAB, BB, CB);
        SCAN_COMP(i, xA, dtA, dAA, BA, CA);
        if (i + 2 < Tt) SCAN_LOAD(i + 2, xA, dtA, dAA, BA, CA);
        SCAN_COMP(i + 1, xB, dtB, dAB, BB, CB);
    }
    #undef SCAN_LOAD
    #undef SCAN_COMP
}

// ---------------- gated RMS norm over 1536 -> fp16 plane --------------------
__global__ void gated_rms_k(const float* __restrict__ ssm_w, int l) {
    __shared__ float sh[32];
    int d = blockIdx.y;
    int row = blockIdx.x;
    const float* y = g_y[d] + (size_t)row * DI;
    const float* z = g_zx[d] + (size_t)row * DPJ;
    __half* out = g_yn16[d] + (size_t)row * DI;
    const float* w = ssm_w + (l * 2 + d) * DI;
    int t = threadIdx.x;
    float g[6], s2 = 0.f;
    #pragma unroll
    for (int i = 0; i < 6; i++) {
        int c = t + 256 * i;
        float gv = y[c] * silu_f(z[c]);
        g[i] = gv;
        s2 += gv * gv;
    }
    float S2 = block_sum(s2, sh);
    float inv = rsqrt_acc(S2 * (1.f / DI) + LEPS);
    #pragma unroll
    for (int i = 0; i < 6; i++) {
        int c = t + 256 * i;
        out[c] = __float2half_rn(g[i] * inv * w[c]);
    }
}

// ---------------- residual add: h += o0 + o1 --------------------------------
__global__ void add3_k() {
    int i = blockIdx.x * 256 + threadIdx.x;
    g_h[i] += g_o[0][i] + g_o[1][i];
}

// ---------------- launcher ---------------------------------------------------
extern "C" void kernel_launch(void* const* d_in, const int* in_sizes, int n_in,
                              void* d_out, int out_size) {
    const float* x          = (const float*)d_in[0];
    const void*  maskp      = d_in[1];
    const float* proj_in_w  = (const float*)d_in[2];
    const float* proj_in_b  = (const float*)d_in[3];
    const float* mask_token = (const float*)d_in[4];
    const float* ln_w       = (const float*)d_in[5];
    const float* ln_b       = (const float*)d_in[6];
    const float* in_proj_w  = (const float*)d_in[7];
    const float* in_proj_b  = (const float*)d_in[8];
    const float* conv_w     = (const float*)d_in[9];
    const float* conv_b     = (const float*)d_in[10];
    const float* dt_bias    = (const float*)d_in[11];
    const float* A_log      = (const float*)d_in[12];
    const float* Dp         = (const float*)d_in[13];
    const float* ssm_w      = (const float*)d_in[14];
    const float* out_proj_w = (const float*)d_in[15];
    const float* fn_w       = (const float*)d_in[16];
    const float* fn_b       = (const float*)d_in[17];
    const float* proj_out_w = (const float*)d_in[18];
    const float* proj_out_b = (const float*)d_in[19];
    float* out = (float*)d_out;

    float *p_h, *p_hn, *p_zx, *p_o;
    __half *p_wih, *p_wil, *p_woh, *p_wol, *p_wpih, *p_wpil, *p_wpoh, *p_wpol;
    __half *p_hn16, *p_yn16, *p_x16;
    cudaGetSymbolAddress((void**)&p_h,    g_h);
    cudaGetSymbolAddress((void**)&p_hn,   g_hn);
    cudaGetSymbolAddress((void**)&p_zx,   g_zx);
    cudaGetSymbolAddress((void**)&p_o,    g_o);
    cudaGetSymbolAddress((void**)&p_wih,  g_wih);
    cudaGetSymbolAddress((void**)&p_wil,  g_wil);
    cudaGetSymbolAddress((void**)&p_woh,  g_woh);
    cudaGetSymbolAddress((void**)&p_wol,  g_wol);
    cudaGetSymbolAddress((void**)&p_wpih, g_wpih);
    cudaGetSymbolAddress((void**)&p_wpil, g_wpil);
    cudaGetSymbolAddress((void**)&p_wpoh, g_wpoh);
    cudaGetSymbolAddress((void**)&p_wpol, g_wpol);
    cudaGetSymbolAddress((void**)&p_hn16, g_hn16);
    cudaGetSymbolAddress((void**)&p_yn16, g_yn16);
    cudaGetSymbolAddress((void**)&p_x16,  g_x16);

    cudaFuncSetAttribute(tgemm_k, cudaFuncAttributeMaxDynamicSharedMemorySize, TG_SMEM);

    detect_mask_k<<<1, 256>>>((const unsigned int*)maskp);

    // weight conversions (transpose + fp16 hi/lo split)
    {
        dim3 tb(32, 8);
        convert_wt_k<<<dim3((DM + 31) / 32, (DIN + 31) / 32), tb>>>(proj_in_w, p_wpih, p_wpil, DIN, DM);
        convert_wt_k<<<dim3((DIN + 31) / 32, (DM + 31) / 32), tb>>>(proj_out_w, p_wpoh, p_wpol, DM, DIN);
        for (int i = 0; i < 4; i++) {
            convert_wt_k<<<dim3((DPJ + 31) / 32, (DM + 31) / 32), tb>>>(
                in_proj_w + (size_t)i * DM * DPJ,
                p_wih + (size_t)i * DPJ * DM, p_wil + (size_t)i * DPJ * DM, DM, DPJ);
            convert_wt_k<<<dim3((DM + 31) / 32, (DI + 31) / 32), tb>>>(
                out_proj_w + (size_t)i * DI * DM,
                p_woh + (size_t)i * DM * DI, p_wol + (size_t)i * DM * DI, DI, DM);
        }
    }

    // h = x @ proj_in_w + b ; apply mask token
    convert_a_k<<<(BT * DIN + 255) / 256, 256>>>(x, p_x16, BT * DIN);
    tgemm_k<<<dim3(DM / 128, BT / 128), 256, TG_SMEM>>>(
        p_x16, p_wpih, p_wpil, proj_in_b, p_h, DM, DIN);
    mask_apply_k<<<BT, DM>>>(maskp, mask_token);

    for (int l = 0; l < 2; l++) {
        layernorm_k<<<BT, 256>>>(p_h, ln_w + l * DM, ln_b + l * DM, nullptr, p_hn16);
        for (int d = 0; d < 2; d++) {
            tgemm_k<<<dim3((DPJ + 127) / 128, BT / 128), 256, TG_SMEM>>>(
                p_hn16,
                p_wih + (size_t)(l * 2 + d) * DPJ * DM,
                p_wil + (size_t)(l * 2 + d) * DPJ * DM,
                in_proj_b + (size_t)(l * 2 + d) * DPJ,
                p_zx + (size_t)d * BT * DPJ, DPJ, DM);
        }
        conv_silu_k<<<dim3((BT * CD + 255) / 256, 2), 256>>>(conv_w, conv_b, l);
        dt_prep_k<<<dim3(BT * NH / 256, 2), 256>>>(dt_bias, A_log, l);
        scan_k<<<dim3(Bb * NH, 2), HD>>>(Dp, l);
        gated_rms_k<<<dim3(BT, 2), 256>>>(ssm_w, l);
        for (int d = 0; d < 2; d++) {
            tgemm_k<<<dim3(DM / 128, BT / 128), 256, TG_SMEM>>>(
                p_yn16 + (size_t)d * BT * DI,
                p_woh + (size_t)(l * 2 + d) * DM * DI,
                p_wol + (size_t)(l * 2 + d) * DM * DI,
                nullptr,
                p_o + (size_t)d * BT * DM, DM, DI);
        }
        add3_k<<<BT * DM / 256, 256>>>();
    }

    // outputs: hidden = LN(h, final); pred = hidden @ proj_out + b
    const int PRED = BT * DIN, HID = BT * DM;
    float* predp = nullptr;
    float* hidp  = nullptr;
    if (out_size >= PRED + HID)      { predp = out; hidp = out + PRED; }
    else if (out_size == PRED)       { predp = out; }
    else                             { hidp = out; }

    layernorm_k<<<BT, 256>>>(p_h, fn_w, fn_b, hidp ? hidp : p_hn, p_hn16);
    if (predp)
        tgemm_k<<<dim3((DIN + 127) / 128, BT / 128), 256, TG_SMEM>>>(
            p_hn16, p_wpoh, p_wpol, proj_out_b, predp, DIN, DM);
}

// round 7
// speedup vs baseline: 2.5612x; 1.0897x over previous
#include <cuda_runtime.h>
#include <cuda_fp16.h>
#include <math.h>
#include <stdint.h>

#define Bb   4
#define Tt   1024
#define BT   4096          // Bb*Tt tokens
#define DM   768
#define DI   1536
#define NH   24
#define HD   64
#define DS   16
#define CD   1568          // D_INNER + 2*D_STATE
#define DPJ  3128          // 2*DI + 2*DS + NH
#define DIN  80
#define LEPS 1e-5f

// ---------------- scratch (device globals; no allocations allowed) ----------
__device__ float g_h  [BT*DM];
__device__ float g_hn [BT*DM];
__device__ float g_zx [2][BT*DPJ];
__device__ float g_xbc[2][BT*CD];
__device__ float g_dt [2][BT*NH];
__device__ float g_dA [2][BT*NH];
__device__ float g_y  [2][BT*DI];
__device__ float g_o  [2][BT*DM];
__device__ int   g_mask_kind;   // 0=int32, 1=float32, 2=uint8/bool
// fp16 weight planes, transposed to [N,K]
__device__ __half g_wih[4][DPJ*DM], g_wil[4][DPJ*DM];
__device__ __half g_woh[4][DM*DI],  g_wol[4][DM*DI];
__device__ __half g_wpih[DM*DIN],   g_wpil[DM*DIN];
__device__ __half g_wpoh[DIN*DM],   g_wpol[DIN*DM];
// fp16 activation planes
__device__ __half g_hn16[BT*DM];
__device__ __half g_yn16[2][BT*DI];
__device__ __half g_x16 [BT*DIN];

// ---------------- generic helpers ----------------
__device__ __forceinline__ float block_sum(float v, float* sh) {
    int lane = threadIdx.x & 31, wid = threadIdx.x >> 5;
    #pragma unroll
    for (int o = 16; o > 0; o >>= 1) v += __shfl_xor_sync(0xffffffffu, v, o);
    if (lane == 0) sh[wid] = v;
    __syncthreads();
    int nw = (blockDim.x + 31) >> 5;
    if (threadIdx.x < 32) {
        float t = (threadIdx.x < nw) ? sh[threadIdx.x] : 0.f;
        #pragma unroll
        for (int o = 16; o > 0; o >>= 1) t += __shfl_xor_sync(0xffffffffu, t, o);
        if (threadIdx.x == 0) sh[0] = t;
    }
    __syncthreads();
    float r = sh[0];
    __syncthreads();
    return r;
}

__device__ __forceinline__ float rsqrt_acc(float a) {
    float r = rsqrtf(a);
    r = r * (1.5f - 0.5f * a * r * r);
    return r;
}

__device__ __forceinline__ float silu_f(float v) {
    return v / (1.f + expf(-v));
}

__device__ __forceinline__ uint32_t smem_u32(const void* p) {
    uint32_t a;
    asm("{ .reg .u64 t; cvta.to.shared.u64 t, %1; cvt.u32.u64 %0, t; }" : "=r"(a) : "l"(p));
    return a;
}

// ---------------- tensor-core GEMM (fp16 x2: A16 @ (Wh+Wl)^T) ---------------
#define SAS   40                // half row stride in smem (80 bytes)
#define PLB   10240             // bytes per plane: 128*40*2
#define BUFB  (3*PLB)           // A, Wh, Wl = 30720 bytes per buffer
#define TG_SMEM (2*BUFB)        // 61440

#define MMA16816(acc, a, b) \
    asm volatile("mma.sync.aligned.m16n8k16.row.col.f32.f16.f16.f32 " \
        "{%0,%1,%2,%3},{%4,%5,%6,%7},{%8,%9},{%0,%1,%2,%3};" \
        : "+f"((acc)[0]), "+f"((acc)[1]), "+f"((acc)[2]), "+f"((acc)[3]) \
        : "r"((a)[0]), "r"((a)[1]), "r"((a)[2]), "r"((a)[3]), \
          "r"((b)[0]), "r"((b)[1]))

#define LDSM4(r, addr) \
    asm volatile("ldmatrix.sync.aligned.m8n8.x4.shared.b16 {%0,%1,%2,%3}, [%4];" \
        : "=r"((r)[0]), "=r"((r)[1]), "=r"((r)[2]), "=r"((r)[3]) : "r"(addr))

__device__ __forceinline__ void cpa16(uint32_t s, const void* g, int szr) {
    asm volatile("cp.async.cg.shared.global [%0], [%1], 16, %2;"
                 :: "r"(s), "l"(__cvta_generic_to_global(g)), "r"(szr) : "memory");
}

__global__ __launch_bounds__(256, 2)
void tgemm_k(const __half* __restrict__ A16,
             const __half* __restrict__ Wh, const __half* __restrict__ Wl,
             const float* __restrict__ bias, float* __restrict__ C,
             int N, int K) {
    extern __shared__ __align__(16) char smraw[];
    const uint32_t sb = smem_u32(smraw);
    const int tid  = threadIdx.x;
    const int lane = tid & 31, warp = tid >> 5;
    const int wr = warp >> 2, wc = warp & 3;
    const int gid = lane >> 2, tq = lane & 3;
    const int row0 = blockIdx.y * 128, n0 = blockIdx.x * 128;

    const int rw = lane & 7;
    const uint32_t aoff = (uint32_t)(((rw + ((lane >> 3) & 1) * 8) * SAS + (lane >> 4) * 8) * 2);
    const uint32_t boff = (uint32_t)(((rw + (lane >> 4) * 8) * SAS + ((lane >> 3) & 1) * 8) * 2);

    float acc[4][4][4];
    #pragma unroll
    for (int mi = 0; mi < 4; mi++)
        #pragma unroll
        for (int ni = 0; ni < 4; ni++)
            #pragma unroll
            for (int e = 0; e < 4; e++) acc[mi][ni][e] = 0.f;

    const int nst = (K + 31) >> 5;

    auto issue = [&](int s, int buf) {
        const int k0 = s * 32;
        const uint32_t base = sb + buf * BUFB;
        #pragma unroll
        for (int i = 0; i < 6; i++) {
            int task = i * 256 + tid;          // 0..1535
            int plane = task >> 9;             // 0:A 1:Wh 2:Wl
            int idx = task & 511;
            int r = idx >> 2, c16 = idx & 3;
            uint32_t dst = base + plane * PLB + (uint32_t)((r * SAS + c16 * 8) * 2);
            int k = k0 + c16 * 8;
            const __half* g;
            int sz = 16;
            if (plane == 0) {
                g = A16 + (size_t)(row0 + r) * K + k;
                if (k + 8 > K) sz = 0;
            } else {
                int n = n0 + r;
                g = (plane == 2 ? Wl : Wh) + (size_t)n * K + k;
                if (k + 8 > K || n >= N) sz = 0;
            }
            if (sz == 0) g = A16;
            cpa16(dst, g, sz);
        }
        asm volatile("cp.async.commit_group;" ::: "memory");
    };

    auto compute = [&](int buf) {
        const uint32_t sA = sb + buf * BUFB;
        const uint32_t sW = sA + PLB;
        #pragma unroll
        for (int kk = 0; kk < 32; kk += 16) {
            uint32_t ah[4][4];
            #pragma unroll
            for (int mi = 0; mi < 4; mi++) {
                uint32_t ab = sA + (uint32_t)(((wr * 64 + mi * 16) * SAS + kk) * 2);
                LDSM4(ah[mi], ab + aoff);
            }
            #pragma unroll
            for (int pr = 0; pr < 2; pr++) {
                uint32_t bh2[4], bl2[4];
                uint32_t bb = sW + (uint32_t)(((wc * 32 + pr * 16) * SAS + kk) * 2);
                LDSM4(bh2, bb + boff);
                LDSM4(bl2, bb + PLB + boff);
                #pragma unroll
                for (int q = 0; q < 2; q++) {
                    int ni = pr * 2 + q;
                    #pragma unroll
                    for (int mi = 0; mi < 4; mi++) {
                        MMA16816(acc[mi][ni], ah[mi], &bh2[q * 2]);
                        MMA16816(acc[mi][ni], ah[mi], &bl2[q * 2]);
                    }
                }
            }
        }
    };

    issue(0, 0);
    for (int s = 0; s < nst; s++) {
        if (s + 1 < nst) {
            issue(s + 1, (s + 1) & 1);
            asm volatile("cp.async.wait_group 1;" ::: "memory");
        } else {
            asm volatile("cp.async.wait_group 0;" ::: "memory");
        }
        __syncthreads();
        compute(s & 1);
        __syncthreads();
    }

    #pragma unroll
    for (int mi = 0; mi < 4; mi++) {
        int row = row0 + wr * 64 + mi * 16 + gid;
        #pragma unroll
        for (int ni = 0; ni < 4; ni++) {
            int col = n0 + wc * 32 + ni * 8 + tq * 2;
            if (col < N) {
                float b0 = bias ? bias[col]     : 0.f;
                float b1 = bias ? bias[col + 1] : 0.f;
                float* c0 = C + (size_t)row * N + col;
                c0[0] = acc[mi][ni][0] + b0;
                c0[1] = acc[mi][ni][1] + b1;
                float* c1 = C + (size_t)(row + 8) * N + col;
                c1[0] = acc[mi][ni][2] + b0;
                c1[1] = acc[mi][ni][3] + b1;
            }
        }
    }
}

// ---------------- weight convert+transpose: src[R,C] fp32 -> dst[C,R] hi/lo -
__global__ void convert_wt_k(const float* __restrict__ src,
                             __half* __restrict__ dhi, __half* __restrict__ dlo,
                             int R, int C) {
    __shared__ float tile[32][33];
    int c0 = blockIdx.x * 32, r0 = blockIdx.y * 32;
    int x = c0 + threadIdx.x;
    #pragma unroll
    for (int j = threadIdx.y; j < 32; j += 8) {
        int r = r0 + j;
        tile[j][threadIdx.x] = (r < R && x < C) ? src[(size_t)r * C + x] : 0.f;
    }
    __syncthreads();
    int xr = r0 + threadIdx.x;
    #pragma unroll
    for (int j = threadIdx.y; j < 32; j += 8) {
        int c = c0 + j;
        if (c < C && xr < R) {
            float v = tile[threadIdx.x][j];
            __half h = __float2half_rn(v);
            __half l = __float2half_rn(v - __half2float(h));
            dhi[(size_t)c * R + xr] = h;
            dlo[(size_t)c * R + xr] = l;
        }
    }
}

// ---------------- activation convert: fp32 -> fp16 --------------------------
__global__ void convert_a_k(const float* __restrict__ src,
                            __half* __restrict__ dst, int n) {
    int i = blockIdx.x * 256 + threadIdx.x;
    if (i < n) dst[i] = __float2half_rn(src[i]);
}

// ---------------- mask dtype detector -----------
__global__ void detect_mask_k(const unsigned int* __restrict__ m) {
    __shared__ int s_ni, s_nf;
    if (threadIdx.x == 0) { s_ni = 0; s_nf = 0; }
    __syncthreads();
    int ni = 0, nf = 0;
    for (int i = threadIdx.x; i < 1024; i += blockDim.x) {
        unsigned w = m[i];
        if (w != 0u && w != 1u)           ni = 1;
        if (w != 0u && w != 0x3F800000u)  nf = 1;
    }
    if (ni) atomicOr(&s_ni, 1);
    if (nf) atomicOr(&s_nf, 1);
    __syncthreads();
    if (threadIdx.x == 0)
        g_mask_kind = (!s_ni) ? 0 : ((!s_nf) ? 1 : 2);
}

__global__ void mask_apply_k(const void* __restrict__ maskp,
                             const float* __restrict__ mask_token) {
    int bt = blockIdx.x;
    int kind = g_mask_kind;
    bool is;
    if (kind == 0)      is = ((const int*)maskp)[bt] != 0;
    else if (kind == 1) is = ((const float*)maskp)[bt] != 0.f;
    else                is = ((const unsigned char*)maskp)[bt] != 0;
    if (is) g_h[bt * DM + threadIdx.x] = mask_token[threadIdx.x];
}

// ---------------- LayerNorm(768) with optional fused residual add -----------
// if o0: v = h + o0 + o1 first; if wb: write v back to h. Outputs fp32/fp16.
__global__ void layernorm_k(float* __restrict__ hbuf,
                            const float* __restrict__ o0, const float* __restrict__ o1,
                            const float* __restrict__ w, const float* __restrict__ b,
                            float* __restrict__ out, __half* __restrict__ out16,
                            int wb) {
    __shared__ float sh[32];
    int row = blockIdx.x;
    float* x = hbuf + (size_t)row * DM;
    int t = threadIdx.x;
    float v0 = x[t], v1 = x[t + 256], v2 = x[t + 512];
    if (o0) {
        const float* a = o0 + (size_t)row * DM;
        const float* c = o1 + (size_t)row * DM;
        v0 += a[t]       + c[t];
        v1 += a[t + 256] + c[t + 256];
        v2 += a[t + 512] + c[t + 512];
        if (wb) { x[t] = v0; x[t + 256] = v1; x[t + 512] = v2; }
    }
    float S  = block_sum(v0 + v1 + v2, sh);
    float mu = S * (1.f / DM);
    float d0 = v0 - mu, d1 = v1 - mu, d2 = v2 - mu;
    float S2 = block_sum(d0 * d0 + d1 * d1 + d2 * d2, sh);
    float inv = rsqrt_acc(S2 * (1.f / DM) + LEPS);
    float r0 = d0 * inv * w[t]       + b[t];
    float r1 = d1 * inv * w[t + 256] + b[t + 256];
    float r2 = d2 * inv * w[t + 512] + b[t + 512];
    if (out) {
        float* o = out + (size_t)row * DM;
        o[t] = r0; o[t + 256] = r1; o[t + 512] = r2;
    }
    if (out16) {
        __half* o = out16 + (size_t)row * DM;
        o[t]       = __float2half_rn(r0);
        o[t + 256] = __float2half_rn(r1);
        o[t + 512] = __float2half_rn(r2);
    }
}

// ---------------- depthwise causal conv7 + silu (per direction) -------------
__global__ void conv_silu_k(const float* __restrict__ cw, const float* __restrict__ cb,
                            int l, int d) {
    int idx = blockIdx.x * 256 + threadIdx.x;
    if (idx >= BT * CD) return;
    int c = idx % CD;
    int btt = idx / CD;
    int b = btt >> 10, t = btt & 1023;
    const float* w = cw + ((size_t)(l * 2 + d) * CD + c) * 7;
    float acc = cb[(l * 2 + d) * CD + c];
    const float* src = g_zx[d];
    if (d == 0) {
        #pragma unroll
        for (int k = 0; k < 7; k++) {
            int tt = t - 6 + k;
            if (tt >= 0) acc = fmaf(w[k], src[(size_t)(b * Tt + tt) * DPJ + 1536 + c], acc);
        }
    } else {
        #pragma unroll
        for (int k = 0; k < 7; k++) {
            int tt = t + 6 - k;
            if (tt < Tt) acc = fmaf(w[k], src[(size_t)(b * Tt + tt) * DPJ + 1536 + c], acc);
        }
    }
    g_xbc[d][idx] = silu_f(acc);
}

// ---------------- dt: softplus + dA (per direction) --------------------------
__global__ void dt_prep_k(const float* __restrict__ dt_bias, const float* __restrict__ A_log,
                          int l, int d) {
    int idx = blockIdx.x * 256 + threadIdx.x;
    int h = idx % NH;
    int bt = idx / NH;
    float raw = g_zx[d][(size_t)bt * DPJ + 3104 + h] + dt_bias[(l * 2 + d) * NH + h];
    float dt = (raw > 20.f) ? raw : log1pf(expf(raw));
    float a = -expf(A_log[(l * 2 + d) * NH + h]);
    g_dt[d][idx] = dt;
    g_dA[d][idx] = expf(a * dt);
}

// ---------------- sequential SSM scan (per direction), reg ping-pong --------
__global__ void scan_k(const float* __restrict__ Dp, int l, int d) {
    const int bh = blockIdx.x;
    const int b  = bh / NH, hh = bh % NH;
    const int p  = threadIdx.x;
    const float* __restrict__ xbc = g_xbc[d];
    const float* __restrict__ dtp = g_dt[d];
    const float* __restrict__ dAp = g_dA[d];
    float* __restrict__ yb = g_y[d];
    const float Dc = Dp[(l * 2 + d) * NH + hh];
    float s[16];
    #pragma unroll
    for (int n = 0; n < 16; n++) s[n] = 0.f;

    float xA, dtA, dAA, BA[16], CA[16];
    float xB, dtB, dAB, BB[16], CB[16];

    #define SCAN_LOAD(i, X, DT, DA, BV, CV) do {                              \
        int t_ = d ? (Tt - 1 - (i)) : (i);                                    \
        int bt_ = b * Tt + t_;                                                \
        const float* row_ = xbc + (size_t)bt_ * CD;                           \
        X  = row_[hh * HD + p];                                               \
        DT = dtp[bt_ * NH + hh];                                              \
        DA = dAp[bt_ * NH + hh];                                              \
        _Pragma("unroll")                                                     \
        for (int q = 0; q < 4; q++) {                                         \
            *(float4*)&BV[q * 4] = *(const float4*)(row_ + 1536 + q * 4);     \
            *(float4*)&CV[q * 4] = *(const float4*)(row_ + 1552 + q * 4);     \
        }                                                                     \
    } while (0)

    #define SCAN_COMP(i, X, DT, DA, BV, CV) do {                              \
        int t_ = d ? (Tt - 1 - (i)) : (i);                                    \
        int bt_ = b * Tt + t_;                                                \
        float c0_ = DT * X;                                                   \
        float a0 = 0.f, a1 = 0.f, a2 = 0.f, a3 = 0.f;                         \
        _Pragma("unroll")                                                     \
        for (int n = 0; n < 16; n += 4) {                                     \
            s[n+0] = fmaf(s[n+0], DA, c0_ * BV[n+0]); a0 = fmaf(s[n+0], CV[n+0], a0); \
            s[n+1] = fmaf(s[n+1], DA, c0_ * BV[n+1]); a1 = fmaf(s[n+1], CV[n+1], a1); \
            s[n+2] = fmaf(s[n+2], DA, c0_ * BV[n+2]); a2 = fmaf(s[n+2], CV[n+2], a2); \
            s[n+3] = fmaf(s[n+3], DA, c0_ * BV[n+3]); a3 = fmaf(s[n+3], CV[n+3], a3); \
        }                                                                     \
        yb[(size_t)bt_ * DI + hh * HD + p] = (a0 + a1) + (a2 + a3) + Dc * X;  \
    } while (0)

    SCAN_LOAD(0, xA, dtA, dAA, BA, CA);
    for (int i = 0; i < Tt; i += 2) {
        SCAN_LOAD(i + 1, xB, dtB, dAB, BB, CB);
        SCAN_COMP(i, xA, dtA, dAA, BA, CA);
        if (i + 2 < Tt) SCAN_LOAD(i + 2, xA, dtA, dAA, BA, CA);
        SCAN_COMP(i + 1, xB, dtB, dAB, BB, CB);
    }
    #undef SCAN_LOAD
    #undef SCAN_COMP
}

// ---------------- gated RMS norm over 1536 -> fp16 plane (per direction) ----
__global__ void gated_rms_k(const float* __restrict__ ssm_w, int l, int d) {
    __shared__ float sh[32];
    int row = blockIdx.x;
    const float* y = g_y[d] + (size_t)row * DI;
    const float* z = g_zx[d] + (size_t)row * DPJ;
    __half* out = g_yn16[d] + (size_t)row * DI;
    const float* w = ssm_w + (l * 2 + d) * DI;
    int t = threadIdx.x;
    float g[6], s2 = 0.f;
    #pragma unroll
    for (int i = 0; i < 6; i++) {
        int c = t + 256 * i;
        float gv = y[c] * silu_f(z[c]);
        g[i] = gv;
        s2 += gv * gv;
    }
    float S2 = block_sum(s2, sh);
    float inv = rsqrt_acc(S2 * (1.f / DI) + LEPS);
    #pragma unroll
    for (int i = 0; i < 6; i++) {
        int c = t + 256 * i;
        out[c] = __float2half_rn(g[i] * inv * w[c]);
    }
}

// ---------------- stream context (created once, outside capture) ------------
struct StreamCtx {
    cudaStream_t s0, s1;
    cudaEvent_t evF, evW, evP, evL[2], evA[2], evB[2];
    int ok;
};
static StreamCtx g_sc = {};

static void sc_init() {
    if (g_sc.ok) return;
    cudaStreamCreateWithFlags(&g_sc.s0, cudaStreamNonBlocking);
    cudaStreamCreateWithFlags(&g_sc.s1, cudaStreamNonBlocking);
    cudaEventCreateWithFlags(&g_sc.evF, cudaEventDisableTiming);
    cudaEventCreateWithFlags(&g_sc.evW, cudaEventDisableTiming);
    cudaEventCreateWithFlags(&g_sc.evP, cudaEventDisableTiming);
    for (int i = 0; i < 2; i++) {
        cudaEventCreateWithFlags(&g_sc.evL[i], cudaEventDisableTiming);
        cudaEventCreateWithFlags(&g_sc.evA[i], cudaEventDisableTiming);
        cudaEventCreateWithFlags(&g_sc.evB[i], cudaEventDisableTiming);
    }
    g_sc.ok = 1;
}

// ---------------- launcher ---------------------------------------------------
extern "C" void kernel_launch(void* const* d_in, const int* in_sizes, int n_in,
                              void* d_out, int out_size) {
    const float* x          = (const float*)d_in[0];
    const void*  maskp      = d_in[1];
    const float* proj_in_w  = (const float*)d_in[2];
    const float* proj_in_b  = (const float*)d_in[3];
    const float* mask_token = (const float*)d_in[4];
    const float* ln_w       = (const float*)d_in[5];
    const float* ln_b       = (const float*)d_in[6];
    const float* in_proj_w  = (const float*)d_in[7];
    const float* in_proj_b  = (const float*)d_in[8];
    const float* conv_w     = (const float*)d_in[9];
    const float* conv_b     = (const float*)d_in[10];
    const float* dt_bias    = (const float*)d_in[11];
    const float* A_log      = (const float*)d_in[12];
    const float* Dp         = (const float*)d_in[13];
    const float* ssm_w      = (const float*)d_in[14];
    const float* out_proj_w = (const float*)d_in[15];
    const float* fn_w       = (const float*)d_in[16];
    const float* fn_b       = (const float*)d_in[17];
    const float* proj_out_w = (const float*)d_in[18];
    const float* proj_out_b = (const float*)d_in[19];
    float* out = (float*)d_out;

    sc_init();
    cudaStream_t S0 = g_sc.s0, S1 = g_sc.s1;
    cudaStream_t STD = (cudaStream_t)0;   // legacy/default (capture origin)

    float *p_h, *p_hn, *p_zx, *p_o;
    __half *p_wih, *p_wil, *p_woh, *p_wol, *p_wpih, *p_wpil, *p_wpoh, *p_wpol;
    __half *p_hn16, *p_yn16, *p_x16;
    cudaGetSymbolAddress((void**)&p_h,    g_h);
    cudaGetSymbolAddress((void**)&p_hn,   g_hn);
    cudaGetSymbolAddress((void**)&p_zx,   g_zx);
    cudaGetSymbolAddress((void**)&p_o,    g_o);
    cudaGetSymbolAddress((void**)&p_wih,  g_wih);
    cudaGetSymbolAddress((void**)&p_wil,  g_wil);
    cudaGetSymbolAddress((void**)&p_woh,  g_woh);
    cudaGetSymbolAddress((void**)&p_wol,  g_wol);
    cudaGetSymbolAddress((void**)&p_wpih, g_wpih);
    cudaGetSymbolAddress((void**)&p_wpil, g_wpil);
    cudaGetSymbolAddress((void**)&p_wpoh, g_wpoh);
    cudaGetSymbolAddress((void**)&p_wpol, g_wpol);
    cudaGetSymbolAddress((void**)&p_hn16, g_hn16);
    cudaGetSymbolAddress((void**)&p_yn16, g_yn16);
    cudaGetSymbolAddress((void**)&p_x16,  g_x16);

    cudaFuncSetAttribute(tgemm_k, cudaFuncAttributeMaxDynamicSharedMemorySize, TG_SMEM);

    dim3 tb(32, 8);

    // ---- fork from capture stream
    detect_mask_k<<<1, 256, 0, STD>>>((const unsigned int*)maskp);
    cudaEventRecord(g_sc.evF, STD);
    cudaStreamWaitEvent(S0, g_sc.evF, 0);
    cudaStreamWaitEvent(S1, g_sc.evF, 0);

    // ---- S0: proj_in path (needs only wpi)
    convert_wt_k<<<dim3((DM + 31) / 32, (DIN + 31) / 32), tb, 0, S0>>>(proj_in_w, p_wpih, p_wpil, DIN, DM);
    convert_a_k<<<(BT * DIN + 255) / 256, 256, 0, S0>>>(x, p_x16, BT * DIN);
    tgemm_k<<<dim3(DM / 128, BT / 128), 256, TG_SMEM, S0>>>(
        p_x16, p_wpih, p_wpil, proj_in_b, p_h, DM, DIN);
    mask_apply_k<<<BT, DM, 0, S0>>>(maskp, mask_token);
    cudaEventRecord(g_sc.evP, S0);

    // ---- S1: all other weight conversions (overlapped)
    convert_wt_k<<<dim3((DIN + 31) / 32, (DM + 31) / 32), tb, 0, S1>>>(proj_out_w, p_wpoh, p_wpol, DM, DIN);
    for (int i = 0; i < 4; i++) {
        convert_wt_k<<<dim3((DPJ + 31) / 32, (DM + 31) / 32), tb, 0, S1>>>(
            in_proj_w + (size_t)i * DM * DPJ,
            p_wih + (size_t)i * DPJ * DM, p_wil + (size_t)i * DPJ * DM, DM, DPJ);
        convert_wt_k<<<dim3((DM + 31) / 32, (DI + 31) / 32), tb, 0, S1>>>(
            out_proj_w + (size_t)i * DI * DM,
            p_woh + (size_t)i * DM * DI, p_wol + (size_t)i * DM * DI, DI, DM);
    }
    cudaEventRecord(g_sc.evW, S1);
    cudaStreamWaitEvent(S0, g_sc.evW, 0);    // S0 needs in/out_proj weights for layers

    // default stream waits for h
    cudaStreamWaitEvent(STD, g_sc.evP, 0);

    for (int l = 0; l < 2; l++) {
        // LN (+ fused residual add of previous layer's out_proj results)
        layernorm_k<<<BT, 256, 0, STD>>>(
            p_h,
            l ? p_o : nullptr, l ? p_o + (size_t)BT * DM : nullptr,
            ln_w + l * DM, ln_b + l * DM, nullptr, p_hn16, 1);
        cudaEventRecord(g_sc.evL[l], STD);

        for (int d = 0; d < 2; d++) {
            cudaStream_t S = d ? S1 : S0;
            cudaStreamWaitEvent(S, g_sc.evL[l], 0);
            tgemm_k<<<dim3((DPJ + 127) / 128, BT / 128), 256, TG_SMEM, S>>>(
                p_hn16,
                p_wih + (size_t)(l * 2 + d) * DPJ * DM,
                p_wil + (size_t)(l * 2 + d) * DPJ * DM,
                in_proj_b + (size_t)(l * 2 + d) * DPJ,
                p_zx + (size_t)d * BT * DPJ, DPJ, DM);
            conv_silu_k<<<(BT * CD + 255) / 256, 256, 0, S>>>(conv_w, conv_b, l, d);
            dt_prep_k<<<BT * NH / 256, 256, 0, S>>>(dt_bias, A_log, l, d);
            scan_k<<<Bb * NH, HD, 0, S>>>(Dp, l, d);
            gated_rms_k<<<BT, 256, 0, S>>>(ssm_w, l, d);
            tgemm_k<<<dim3(DM / 128, BT / 128), 256, TG_SMEM, S>>>(
                p_yn16 + (size_t)d * BT * DI,
                p_woh + (size_t)(l * 2 + d) * DM * DI,
                p_wol + (size_t)(l * 2 + d) * DM * DI,
                nullptr,
                p_o + (size_t)d * BT * DM, DM, DI);
            cudaEventRecord(d ? g_sc.evB[l] : g_sc.evA[l], S);
        }
        cudaStreamWaitEvent(STD, g_sc.evA[l], 0);
        cudaStreamWaitEvent(STD, g_sc.evB[l], 0);
    }

    // outputs: hidden = LN(h + o0 + o1, final); pred = hidden16 @ proj_out + b
    const int PRED = BT * DIN, HID = BT * DM;
    float* predp = nullptr;
    float* hidp  = nullptr;
    if (out_size >= PRED + HID)      { predp = out; hidp = out + PRED; }
    else if (out_size == PRED)       { predp = out; }
    else                             { hidp = out; }

    layernorm_k<<<BT, 256, 0, STD>>>(
        p_h, p_o, p_o + (size_t)BT * DM,
        fn_w, fn_b, hidp ? hidp : p_hn, p_hn16, 0);
    if (predp)
        tgemm_k<<<dim3((DIN + 127) / 128, BT / 128), 256, TG_SMEM, STD>>>(
            p_hn16, p_wpoh, p_wpol, proj_out_b, predp, DIN, DM);
}

// round 8
// speedup vs baseline: 2.5783x; 1.0067x over previous
#include <cuda_runtime.h>
#include <cuda_fp16.h>
#include <math.h>
#include <stdint.h>

#define Bb   4
#define Tt   1024
#define BT   4096          // Bb*Tt tokens
#define DM   768
#define DI   1536
#define NH   24
#define HD   64
#define DS   16
#define CD   1568          // D_INNER + 2*D_STATE
#define DPJ  3128          // 2*DI + 2*DS + NH
#define DIN  80
#define LEPS 1e-5f

// ---------------- scratch (device globals; no allocations allowed) ----------
__device__ float g_h  [BT*DM];
__device__ float g_hn [BT*DM];
__device__ float g_zx [2][BT*DPJ];
__device__ float g_xbc[2][BT*CD];
__device__ float g_dt [2][BT*NH];
__device__ float g_dA [2][BT*NH];
__device__ float g_y  [2][BT*DI];
__device__ float g_o  [2][BT*DM];
__device__ int   g_mask_kind;   // 0=int32, 1=float32, 2=uint8/bool
// fp16 weight planes, transposed to [N,K]
__device__ __half g_wih[4][DPJ*DM], g_wil[4][DPJ*DM];
__device__ __half g_woh[4][DM*DI],  g_wol[4][DM*DI];
__device__ __half g_wpih[DM*DIN],   g_wpil[DM*DIN];
__device__ __half g_wpoh[DIN*DM],   g_wpol[DIN*DM];
// fp16 activation planes
__device__ __half g_hn16[BT*DM];
__device__ __half g_yn16[2][BT*DI];
__device__ __half g_x16 [BT*DIN];

// ---------------- generic helpers ----------------
__device__ __forceinline__ float block_sum(float v, float* sh) {
    int lane = threadIdx.x & 31, wid = threadIdx.x >> 5;
    #pragma unroll
    for (int o = 16; o > 0; o >>= 1) v += __shfl_xor_sync(0xffffffffu, v, o);
    if (lane == 0) sh[wid] = v;
    __syncthreads();
    int nw = (blockDim.x + 31) >> 5;
    if (threadIdx.x < 32) {
        float t = (threadIdx.x < nw) ? sh[threadIdx.x] : 0.f;
        #pragma unroll
        for (int o = 16; o > 0; o >>= 1) t += __shfl_xor_sync(0xffffffffu, t, o);
        if (threadIdx.x == 0) sh[0] = t;
    }
    __syncthreads();
    float r = sh[0];
    __syncthreads();
    return r;
}

__device__ __forceinline__ float rsqrt_acc(float a) {
    float r = rsqrtf(a);
    r = r * (1.5f - 0.5f * a * r * r);
    return r;
}

__device__ __forceinline__ float silu_f(float v) {
    return v / (1.f + expf(-v));
}

__device__ __forceinline__ uint32_t smem_u32(const void* p) {
    uint32_t a;
    asm("{ .reg .u64 t; cvta.to.shared.u64 t, %1; cvt.u32.u64 %0, t; }" : "=r"(a) : "l"(p));
    return a;
}

// ---------------- tensor-core GEMM (fp16 x2: A16 @ (Wh+Wl)^T) ---------------
#define SAS   40                // half row stride in smem (80 bytes)
#define PLB   10240             // bytes per plane: 128*40*2
#define BUFB  (3*PLB)           // A, Wh, Wl = 30720 bytes per buffer
#define TG_SMEM (2*BUFB)        // 61440

#define MMA16816(acc, a, b) \
    asm volatile("mma.sync.aligned.m16n8k16.row.col.f32.f16.f16.f32 " \
        "{%0,%1,%2,%3},{%4,%5,%6,%7},{%8,%9},{%0,%1,%2,%3};" \
        : "+f"((acc)[0]), "+f"((acc)[1]), "+f"((acc)[2]), "+f"((acc)[3]) \
        : "r"((a)[0]), "r"((a)[1]), "r"((a)[2]), "r"((a)[3]), \
          "r"((b)[0]), "r"((b)[1]))

#define LDSM4(r, addr) \
    asm volatile("ldmatrix.sync.aligned.m8n8.x4.shared.b16 {%0,%1,%2,%3}, [%4];" \
        : "=r"((r)[0]), "=r"((r)[1]), "=r"((r)[2]), "=r"((r)[3]) : "r"(addr))

__device__ __forceinline__ void cpa16(uint32_t s, const void* g, int szr) {
    asm volatile("cp.async.cg.shared.global [%0], [%1], 16, %2;"
                 :: "r"(s), "l"(__cvta_generic_to_global(g)), "r"(szr) : "memory");
}

__global__ __launch_bounds__(256, 2)
void tgemm_k(const __half* __restrict__ A16,
             const __half* __restrict__ Wh, const __half* __restrict__ Wl,
             const float* __restrict__ bias, float* __restrict__ C,
             int N, int K) {
    extern __shared__ __align__(16) char smraw[];
    const uint32_t sb = smem_u32(smraw);
    const int tid  = threadIdx.x;
    const int lane = tid & 31, warp = tid >> 5;
    const int wr = warp >> 2, wc = warp & 3;
    const int gid = lane >> 2, tq = lane & 3;
    const int row0 = blockIdx.y * 128, n0 = blockIdx.x * 128;

    const int rw = lane & 7;
    const uint32_t aoff = (uint32_t)(((rw + ((lane >> 3) & 1) * 8) * SAS + (lane >> 4) * 8) * 2);
    const uint32_t boff = (uint32_t)(((rw + (lane >> 4) * 8) * SAS + ((lane >> 3) & 1) * 8) * 2);

    float acc[4][4][4];
    #pragma unroll
    for (int mi = 0; mi < 4; mi++)
        #pragma unroll
        for (int ni = 0; ni < 4; ni++)
            #pragma unroll
            for (int e = 0; e < 4; e++) acc[mi][ni][e] = 0.f;

    const int nst = (K + 31) >> 5;

    auto issue = [&](int s, int buf) {
        const int k0 = s * 32;
        const uint32_t base = sb + buf * BUFB;
        #pragma unroll
        for (int i = 0; i < 6; i++) {
            int task = i * 256 + tid;          // 0..1535
            int plane = task >> 9;             // 0:A 1:Wh 2:Wl
            int idx = task & 511;
            int r = idx >> 2, c16 = idx & 3;
            uint32_t dst = base + plane * PLB + (uint32_t)((r * SAS + c16 * 8) * 2);
            int k = k0 + c16 * 8;
            const __half* g;
            int sz = 16;
            if (plane == 0) {
                g = A16 + (size_t)(row0 + r) * K + k;
                if (k + 8 > K) sz = 0;
            } else {
                int n = n0 + r;
                g = (plane == 2 ? Wl : Wh) + (size_t)n * K + k;
                if (k + 8 > K || n >= N) sz = 0;
            }
            if (sz == 0) g = A16;
            cpa16(dst, g, sz);
        }
        asm volatile("cp.async.commit_group;" ::: "memory");
    };

    auto compute = [&](int buf) {
        const uint32_t sA = sb + buf * BUFB;
        const uint32_t sW = sA + PLB;
        #pragma unroll
        for (int kk = 0; kk < 32; kk += 16) {
            uint32_t ah[4][4];
            #pragma unroll
            for (int mi = 0; mi < 4; mi++) {
                uint32_t ab = sA + (uint32_t)(((wr * 64 + mi * 16) * SAS + kk) * 2);
                LDSM4(ah[mi], ab + aoff);
            }
            #pragma unroll
            for (int pr = 0; pr < 2; pr++) {
                uint32_t bh2[4], bl2[4];
                uint32_t bb = sW + (uint32_t)(((wc * 32 + pr * 16) * SAS + kk) * 2);
                LDSM4(bh2, bb + boff);
                LDSM4(bl2, bb + PLB + boff);
                #pragma unroll
                for (int q = 0; q < 2; q++) {
                    int ni = pr * 2 + q;
                    #pragma unroll
                    for (int mi = 0; mi < 4; mi++) {
                        MMA16816(acc[mi][ni], ah[mi], &bh2[q * 2]);
                        MMA16816(acc[mi][ni], ah[mi], &bl2[q * 2]);
                    }
                }
            }
        }
    };

    issue(0, 0);
    for (int s = 0; s < nst; s++) {
        if (s + 1 < nst) {
            issue(s + 1, (s + 1) & 1);
            asm volatile("cp.async.wait_group 1;" ::: "memory");
        } else {
            asm volatile("cp.async.wait_group 0;" ::: "memory");
        }
        __syncthreads();
        compute(s & 1);
        __syncthreads();
    }

    #pragma unroll
    for (int mi = 0; mi < 4; mi++) {
        int row = row0 + wr * 64 + mi * 16 + gid;
        #pragma unroll
        for (int ni = 0; ni < 4; ni++) {
            int col = n0 + wc * 32 + ni * 8 + tq * 2;
            if (col < N) {
                float b0 = bias ? bias[col]     : 0.f;
                float b1 = bias ? bias[col + 1] : 0.f;
                float* c0 = C + (size_t)row * N + col;
                c0[0] = acc[mi][ni][0] + b0;
                c0[1] = acc[mi][ni][1] + b1;
                float* c1 = C + (size_t)(row + 8) * N + col;
                c1[0] = acc[mi][ni][2] + b0;
                c1[1] = acc[mi][ni][3] + b1;
            }
        }
    }
}

// ---------------- weight convert+transpose: src[R,C] fp32 -> dst[C,R] hi/lo -
__global__ void convert_wt_k(const float* __restrict__ src,
                             __half* __restrict__ dhi, __half* __restrict__ dlo,
                             int R, int C) {
    __shared__ float tile[32][33];
    int c0 = blockIdx.x * 32, r0 = blockIdx.y * 32;
    int x = c0 + threadIdx.x;
    #pragma unroll
    for (int j = threadIdx.y; j < 32; j += 8) {
        int r = r0 + j;
        tile[j][threadIdx.x] = (r < R && x < C) ? src[(size_t)r * C + x] : 0.f;
    }
    __syncthreads();
    int xr = r0 + threadIdx.x;
    #pragma unroll
    for (int j = threadIdx.y; j < 32; j += 8) {
        int c = c0 + j;
        if (c < C && xr < R) {
            float v = tile[threadIdx.x][j];
            __half h = __float2half_rn(v);
            __half l = __float2half_rn(v - __half2float(h));
            dhi[(size_t)c * R + xr] = h;
            dlo[(size_t)c * R + xr] = l;
        }
    }
}

// ---------------- activation convert: fp32 -> fp16 --------------------------
__global__ void convert_a_k(const float* __restrict__ src,
                            __half* __restrict__ dst, int n) {
    int i = blockIdx.x * 256 + threadIdx.x;
    if (i < n) dst[i] = __float2half_rn(src[i]);
}

// ---------------- mask dtype detector -----------
__global__ void detect_mask_k(const unsigned int* __restrict__ m) {
    __shared__ int s_ni, s_nf;
    if (threadIdx.x == 0) { s_ni = 0; s_nf = 0; }
    __syncthreads();
    int ni = 0, nf = 0;
    for (int i = threadIdx.x; i < 1024; i += blockDim.x) {
        unsigned w = m[i];
        if (w != 0u && w != 1u)           ni = 1;
        if (w != 0u && w != 0x3F800000u)  nf = 1;
    }
    if (ni) atomicOr(&s_ni, 1);
    if (nf) atomicOr(&s_nf, 1);
    __syncthreads();
    if (threadIdx.x == 0)
        g_mask_kind = (!s_ni) ? 0 : ((!s_nf) ? 1 : 2);
}

__global__ void mask_apply_k(const void* __restrict__ maskp,
                             const float* __restrict__ mask_token) {
    int bt = blockIdx.x;
    int kind = g_mask_kind;
    bool is;
    if (kind == 0)      is = ((const int*)maskp)[bt] != 0;
    else if (kind == 1) is = ((const float*)maskp)[bt] != 0.f;
    else                is = ((const unsigned char*)maskp)[bt] != 0;
    if (is) g_h[bt * DM + threadIdx.x] = mask_token[threadIdx.x];
}

// ---------------- LayerNorm(768) with optional fused residual add -----------
__global__ void layernorm_k(float* __restrict__ hbuf,
                            const float* __restrict__ o0, const float* __restrict__ o1,
                            const float* __restrict__ w, const float* __restrict__ b,
                            float* __restrict__ out, __half* __restrict__ out16,
                            int wb) {
    __shared__ float sh[32];
    int row = blockIdx.x;
    float* x = hbuf + (size_t)row * DM;
    int t = threadIdx.x;
    float v0 = x[t], v1 = x[t + 256], v2 = x[t + 512];
    if (o0) {
        const float* a = o0 + (size_t)row * DM;
        const float* c = o1 + (size_t)row * DM;
        v0 += a[t]       + c[t];
        v1 += a[t + 256] + c[t + 256];
        v2 += a[t + 512] + c[t + 512];
        if (wb) { x[t] = v0; x[t + 256] = v1; x[t + 512] = v2; }
    }
    float S  = block_sum(v0 + v1 + v2, sh);
    float mu = S * (1.f / DM);
    float d0 = v0 - mu, d1 = v1 - mu, d2 = v2 - mu;
    float S2 = block_sum(d0 * d0 + d1 * d1 + d2 * d2, sh);
    float inv = rsqrt_acc(S2 * (1.f / DM) + LEPS);
    float r0 = d0 * inv * w[t]       + b[t];
    float r1 = d1 * inv * w[t + 256] + b[t + 256];
    float r2 = d2 * inv * w[t + 512] + b[t + 512];
    if (out) {
        float* o = out + (size_t)row * DM;
        o[t] = r0; o[t + 256] = r1; o[t + 512] = r2;
    }
    if (out16) {
        __half* o = out16 + (size_t)row * DM;
        o[t]       = __float2half_rn(r0);
        o[t + 256] = __float2half_rn(r1);
        o[t + 512] = __float2half_rn(r2);
    }
}

// ---------------- depthwise causal conv7 + silu (per direction) -------------
__global__ void conv_silu_k(const float* __restrict__ cw, const float* __restrict__ cb,
                            int l, int d) {
    int idx = blockIdx.x * 256 + threadIdx.x;
    if (idx >= BT * CD) return;
    int c = idx % CD;
    int btt = idx / CD;
    int b = btt >> 10, t = btt & 1023;
    const float* w = cw + ((size_t)(l * 2 + d) * CD + c) * 7;
    float acc = cb[(l * 2 + d) * CD + c];
    const float* src = g_zx[d];
    if (d == 0) {
        #pragma unroll
        for (int k = 0; k < 7; k++) {
            int tt = t - 6 + k;
            if (tt >= 0) acc = fmaf(w[k], src[(size_t)(b * Tt + tt) * DPJ + 1536 + c], acc);
        }
    } else {
        #pragma unroll
        for (int k = 0; k < 7; k++) {
            int tt = t + 6 - k;
            if (tt < Tt) acc = fmaf(w[k], src[(size_t)(b * Tt + tt) * DPJ + 1536 + c], acc);
        }
    }
    g_xbc[d][idx] = silu_f(acc);
}

// ---------------- dt: softplus + dA (per direction) --------------------------
__global__ void dt_prep_k(const float* __restrict__ dt_bias, const float* __restrict__ A_log,
                          int l, int d) {
    int idx = blockIdx.x * 256 + threadIdx.x;
    int h = idx % NH;
    int bt = idx / NH;
    float raw = g_zx[d][(size_t)bt * DPJ + 3104 + h] + dt_bias[(l * 2 + d) * NH + h];
    float dt = (raw > 20.f) ? raw : log1pf(expf(raw));
    float a = -expf(A_log[(l * 2 + d) * NH + h]);
    g_dt[d][idx] = dt;
    g_dA[d][idx] = expf(a * dt);
}

// ---------------- sequential SSM scan (per direction), reg ping-pong --------
__global__ void scan_k(const float* __restrict__ Dp, int l, int d) {
    const int bh = blockIdx.x;
    const int b  = bh / NH, hh = bh % NH;
    const int p  = threadIdx.x;
    const float* __restrict__ xbc = g_xbc[d];
    const float* __restrict__ dtp = g_dt[d];
    const float* __restrict__ dAp = g_dA[d];
    float* __restrict__ yb = g_y[d];
    const float Dc = Dp[(l * 2 + d) * NH + hh];
    float s[16];
    #pragma unroll
    for (int n = 0; n < 16; n++) s[n] = 0.f;

    float xA, dtA, dAA, BA[16], CA[16];
    float xB, dtB, dAB, BB[16], CB[16];

    #define SCAN_LOAD(i, X, DT, DA, BV, CV) do {                              \
        int t_ = d ? (Tt - 1 - (i)) : (i);                                    \
        int bt_ = b * Tt + t_;                                                \
        const float* row_ = xbc + (size_t)bt_ * CD;                           \
        X  = row_[hh * HD + p];                                               \
        DT = dtp[bt_ * NH + hh];                                              \
        DA = dAp[bt_ * NH + hh];                                              \
        _Pragma("unroll")                                                     \
        for (int q = 0; q < 4; q++) {                                         \
            *(float4*)&BV[q * 4] = *(const float4*)(row_ + 1536 + q * 4);     \
            *(float4*)&CV[q * 4] = *(const float4*)(row_ + 1552 + q * 4);     \
        }                                                                     \
    } while (0)

    #define SCAN_COMP(i, X, DT, DA, BV, CV) do {                              \
        int t_ = d ? (Tt - 1 - (i)) : (i);                                    \
        int bt_ = b * Tt + t_;                                                \
        float c0_ = DT * X;                                                   \
        float a0 = 0.f, a1 = 0.f, a2 = 0.f, a3 = 0.f;                         \
        _Pragma("unroll")                                                     \
        for (int n = 0; n < 16; n += 4) {                                     \
            s[n+0] = fmaf(s[n+0], DA, c0_ * BV[n+0]); a0 = fmaf(s[n+0], CV[n+0], a0); \
            s[n+1] = fmaf(s[n+1], DA, c0_ * BV[n+1]); a1 = fmaf(s[n+1], CV[n+1], a1); \
            s[n+2] = fmaf(s[n+2], DA, c0_ * BV[n+2]); a2 = fmaf(s[n+2], CV[n+2], a2); \
            s[n+3] = fmaf(s[n+3], DA, c0_ * BV[n+3]); a3 = fmaf(s[n+3], CV[n+3], a3); \
        }                                                                     \
        yb[(size_t)bt_ * DI + hh * HD + p] = (a0 + a1) + (a2 + a3) + Dc * X;  \
    } while (0)

    SCAN_LOAD(0, xA, dtA, dAA, BA, CA);
    for (int i = 0; i < Tt; i += 2) {
        SCAN_LOAD(i + 1, xB, dtB, dAB, BB, CB);
        SCAN_COMP(i, xA, dtA, dAA, BA, CA);
        if (i + 2 < Tt) SCAN_LOAD(i + 2, xA, dtA, dAA, BA, CA);
        SCAN_COMP(i + 1, xB, dtB, dAB, BB, CB);
    }
    #undef SCAN_LOAD
    #undef SCAN_COMP
}

// ---------------- gated RMS norm over 1536 -> fp16 plane (per direction) ----
__global__ void gated_rms_k(const float* __restrict__ ssm_w, int l, int d) {
    __shared__ float sh[32];
    int row = blockIdx.x;
    const float* y = g_y[d] + (size_t)row * DI;
    const float* z = g_zx[d] + (size_t)row * DPJ;
    __half* out = g_yn16[d] + (size_t)row * DI;
    const float* w = ssm_w + (l * 2 + d) * DI;
    int t = threadIdx.x;
    float g[6], s2 = 0.f;
    #pragma unroll
    for (int i = 0; i < 6; i++) {
        int c = t + 256 * i;
        float gv = y[c] * silu_f(z[c]);
        g[i] = gv;
        s2 += gv * gv;
    }
    float S2 = block_sum(s2, sh);
    float inv = rsqrt_acc(S2 * (1.f / DI) + LEPS);
    #pragma unroll
    for (int i = 0; i < 6; i++) {
        int c = t + 256 * i;
        out[c] = __float2half_rn(g[i] * inv * w[c]);
    }
}

// ---------------- stream context (created once, outside capture) ------------
struct StreamCtx {
    cudaStream_t s0, s1, s2;
    cudaEvent_t evF, evP, evPO;
    cudaEvent_t evCI[4], evCO[4];
    cudaEvent_t evL[2], evI0[2], evI1[2], evA[2], evB[2];
    int ok;
};
static StreamCtx g_sc = {};

static void sc_init() {
    if (g_sc.ok) return;
    cudaStreamCreateWithFlags(&g_sc.s0, cudaStreamNonBlocking);
    cudaStreamCreateWithFlags(&g_sc.s1, cudaStreamNonBlocking);
    cudaStreamCreateWithFlags(&g_sc.s2, cudaStreamNonBlocking);
    cudaEventCreateWithFlags(&g_sc.evF,  cudaEventDisableTiming);
    cudaEventCreateWithFlags(&g_sc.evP,  cudaEventDisableTiming);
    cudaEventCreateWithFlags(&g_sc.evPO, cudaEventDisableTiming);
    for (int i = 0; i < 4; i++) {
        cudaEventCreateWithFlags(&g_sc.evCI[i], cudaEventDisableTiming);
        cudaEventCreateWithFlags(&g_sc.evCO[i], cudaEventDisableTiming);
    }
    for (int i = 0; i < 2; i++) {
        cudaEventCreateWithFlags(&g_sc.evL[i],  cudaEventDisableTiming);
        cudaEventCreateWithFlags(&g_sc.evI0[i], cudaEventDisableTiming);
        cudaEventCreateWithFlags(&g_sc.evI1[i], cudaEventDisableTiming);
        cudaEventCreateWithFlags(&g_sc.evA[i],  cudaEventDisableTiming);
        cudaEventCreateWithFlags(&g_sc.evB[i],  cudaEventDisableTiming);
    }
    g_sc.ok = 1;
}

// ---------------- launcher ---------------------------------------------------
extern "C" void kernel_launch(void* const* d_in, const int* in_sizes, int n_in,
                              void* d_out, int out_size) {
    const float* x          = (const float*)d_in[0];
    const void*  maskp      = d_in[1];
    const float* proj_in_w  = (const float*)d_in[2];
    const float* proj_in_b  = (const float*)d_in[3];
    const float* mask_token = (const float*)d_in[4];
    const float* ln_w       = (const float*)d_in[5];
    const float* ln_b       = (const float*)d_in[6];
    const float* in_proj_w  = (const float*)d_in[7];
    const float* in_proj_b  = (const float*)d_in[8];
    const float* conv_w     = (const float*)d_in[9];
    const float* conv_b     = (const float*)d_in[10];
    const float* dt_bias    = (const float*)d_in[11];
    const float* A_log      = (const float*)d_in[12];
    const float* Dp         = (const float*)d_in[13];
    const float* ssm_w      = (const float*)d_in[14];
    const float* out_proj_w = (const float*)d_in[15];
    const float* fn_w       = (const float*)d_in[16];
    const float* fn_b       = (const float*)d_in[17];
    const float* proj_out_w = (const float*)d_in[18];
    const float* proj_out_b = (const float*)d_in[19];
    float* out = (float*)d_out;

    sc_init();
    cudaStream_t S0 = g_sc.s0, S1 = g_sc.s1, S2 = g_sc.s2;
    cudaStream_t STD = (cudaStream_t)0;   // legacy/default (capture origin)

    float *p_h, *p_hn, *p_zx, *p_o;
    __half *p_wih, *p_wil, *p_woh, *p_wol, *p_wpih, *p_wpil, *p_wpoh, *p_wpol;
    __half *p_hn16, *p_yn16, *p_x16;
    cudaGetSymbolAddress((void**)&p_h,    g_h);
    cudaGetSymbolAddress((void**)&p_hn,   g_hn);
    cudaGetSymbolAddress((void**)&p_zx,   g_zx);
    cudaGetSymbolAddress((void**)&p_o,    g_o);
    cudaGetSymbolAddress((void**)&p_wih,  g_wih);
    cudaGetSymbolAddress((void**)&p_wil,  g_wil);
    cudaGetSymbolAddress((void**)&p_woh,  g_woh);
    cudaGetSymbolAddress((void**)&p_wol,  g_wol);
    cudaGetSymbolAddress((void**)&p_wpih, g_wpih);
    cudaGetSymbolAddress((void**)&p_wpil, g_wpil);
    cudaGetSymbolAddress((void**)&p_wpoh, g_wpoh);
    cudaGetSymbolAddress((void**)&p_wpol, g_wpol);
    cudaGetSymbolAddress((void**)&p_hn16, g_hn16);
    cudaGetSymbolAddress((void**)&p_yn16, g_yn16);
    cudaGetSymbolAddress((void**)&p_x16,  g_x16);

    cudaFuncSetAttribute(tgemm_k, cudaFuncAttributeMaxDynamicSharedMemorySize, TG_SMEM);

    dim3 tb(32, 8);

    // ---- fork from capture stream
    detect_mask_k<<<1, 256, 0, STD>>>((const unsigned int*)maskp);
    cudaEventRecord(g_sc.evF, STD);
    cudaStreamWaitEvent(S0, g_sc.evF, 0);
    cudaStreamWaitEvent(S1, g_sc.evF, 0);
    cudaStreamWaitEvent(S2, g_sc.evF, 0);

    // ---- S2: weight conversions, priority order (layer-0 in_proj first)
    for (int i = 0; i < 2; i++) {           // wih[0], wih[1]
        convert_wt_k<<<dim3((DPJ + 31) / 32, (DM + 31) / 32), tb, 0, S2>>>(
            in_proj_w + (size_t)i * DM * DPJ,
            p_wih + (size_t)i * DPJ * DM, p_wil + (size_t)i * DPJ * DM, DM, DPJ);
        cudaEventRecord(g_sc.evCI[i], S2);
    }
    for (int i = 0; i < 2; i++) {           // woh[0], woh[1]
        convert_wt_k<<<dim3((DM + 31) / 32, (DI + 31) / 32), tb, 0, S2>>>(
            out_proj_w + (size_t)i * DI * DM,
            p_woh + (size_t)i * DM * DI, p_wol + (size_t)i * DM * DI, DI, DM);
        cudaEventRecord(g_sc.evCO[i], S2);
    }
    for (int i = 2; i < 4; i++) {           // wih[2], wih[3]
        convert_wt_k<<<dim3((DPJ + 31) / 32, (DM + 31) / 32), tb, 0, S2>>>(
            in_proj_w + (size_t)i * DM * DPJ,
            p_wih + (size_t)i * DPJ * DM, p_wil + (size_t)i * DPJ * DM, DM, DPJ);
        cudaEventRecord(g_sc.evCI[i], S2);
    }
    for (int i = 2; i < 4; i++) {           // woh[2], woh[3]
        convert_wt_k<<<dim3((DM + 31) / 32, (DI + 31) / 32), tb, 0, S2>>>(
            out_proj_w + (size_t)i * DI * DM,
            p_woh + (size_t)i * DM * DI, p_wol + (size_t)i * DM * DI, DI, DM);
        cudaEventRecord(g_sc.evCO[i], S2);
    }
    convert_wt_k<<<dim3((DIN + 31) / 32, (DM + 31) / 32), tb, 0, S2>>>(
        proj_out_w, p_wpoh, p_wpol, DM, DIN);
    cudaEventRecord(g_sc.evPO, S2);

    // ---- S0: proj_in path
    convert_wt_k<<<dim3((DM + 31) / 32, (DIN + 31) / 32), tb, 0, S0>>>(proj_in_w, p_wpih, p_wpil, DIN, DM);
    convert_a_k<<<(BT * DIN + 255) / 256, 256, 0, S0>>>(x, p_x16, BT * DIN);
    tgemm_k<<<dim3(DM / 128, BT / 128), 256, TG_SMEM, S0>>>(
        p_x16, p_wpih, p_wpil, proj_in_b, p_h, DM, DIN);
    mask_apply_k<<<BT, DM, 0, S0>>>(maskp, mask_token);
    cudaEventRecord(g_sc.evP, S0);

    // default stream waits for h
    cudaStreamWaitEvent(STD, g_sc.evP, 0);

    for (int l = 0; l < 2; l++) {
        // LN (+ fused residual add of previous layer's out_proj results)
        layernorm_k<<<BT, 256, 0, STD>>>(
            p_h,
            l ? p_o : nullptr, l ? p_o + (size_t)BT * DM : nullptr,
            ln_w + l * DM, ln_b + l * DM, nullptr, p_hn16, 1);
        cudaEventRecord(g_sc.evL[l], STD);

        // ---- d0 on S0
        cudaStreamWaitEvent(S0, g_sc.evL[l], 0);
        cudaStreamWaitEvent(S0, g_sc.evCI[l * 2 + 0], 0);
        tgemm_k<<<dim3((DPJ + 127) / 128, BT / 128), 256, TG_SMEM, S0>>>(
            p_hn16,
            p_wih + (size_t)(l * 2 + 0) * DPJ * DM,
            p_wil + (size_t)(l * 2 + 0) * DPJ * DM,
            in_proj_b + (size_t)(l * 2 + 0) * DPJ,
            p_zx, DPJ, DM);
        cudaEventRecord(g_sc.evI0[l], S0);
        conv_silu_k<<<(BT * CD + 255) / 256, 256, 0, S0>>>(conv_w, conv_b, l, 0);
        dt_prep_k<<<BT * NH / 256, 256, 0, S0>>>(dt_bias, A_log, l, 0);
        scan_k<<<Bb * NH, HD, 0, S0>>>(Dp, l, 0);
        gated_rms_k<<<BT, 256, 0, S0>>>(ssm_w, l, 0);

        // ---- d1 on S1: in_proj serialized after d0's in_proj (skew)
        cudaStreamWaitEvent(S1, g_sc.evL[l], 0);
        cudaStreamWaitEvent(S1, g_sc.evCI[l * 2 + 1], 0);
        cudaStreamWaitEvent(S1, g_sc.evI0[l], 0);
        tgemm_k<<<dim3((DPJ + 127) / 128, BT / 128), 256, TG_SMEM, S1>>>(
            p_hn16,
            p_wih + (size_t)(l * 2 + 1) * DPJ * DM,
            p_wil + (size_t)(l * 2 + 1) * DPJ * DM,
            in_proj_b + (size_t)(l * 2 + 1) * DPJ,
            p_zx + (size_t)BT * DPJ, DPJ, DM);
        cudaEventRecord(g_sc.evI1[l], S1);
        conv_silu_k<<<(BT * CD + 255) / 256, 256, 0, S1>>>(conv_w, conv_b, l, 1);
        dt_prep_k<<<BT * NH / 256, 256, 0, S1>>>(dt_bias, A_log, l, 1);
        scan_k<<<Bb * NH, HD, 0, S1>>>(Dp, l, 1);
        gated_rms_k<<<BT, 256, 0, S1>>>(ssm_w, l, 1);

        // ---- out_proj d0: wait until in_proj(d1) finished (keep it at full rate)
        cudaStreamWaitEvent(S0, g_sc.evI1[l], 0);
        cudaStreamWaitEvent(S0, g_sc.evCO[l * 2 + 0], 0);
        tgemm_k<<<dim3(DM / 128, BT / 128), 256, TG_SMEM, S0>>>(
            p_yn16,
            p_woh + (size_t)(l * 2 + 0) * DM * DI,
            p_wol + (size_t)(l * 2 + 0) * DM * DI,
            nullptr, p_o, DM, DI);
        cudaEventRecord(g_sc.evA[l], S0);

        // ---- out_proj d1
        cudaStreamWaitEvent(S1, g_sc.evCO[l * 2 + 1], 0);
        tgemm_k<<<dim3(DM / 128, BT / 128), 256, TG_SMEM, S1>>>(
            p_yn16 + (size_t)BT * DI,
            p_woh + (size_t)(l * 2 + 1) * DM * DI,
            p_wol + (size_t)(l * 2 + 1) * DM * DI,
            nullptr, p_o + (size_t)BT * DM, DM, DI);
        cudaEventRecord(g_sc.evB[l], S1);

        cudaStreamWaitEvent(STD, g_sc.evA[l], 0);
        cudaStreamWaitEvent(STD, g_sc.evB[l], 0);
    }

    // outputs: hidden = LN(h + o0 + o1, final); pred = hidden16 @ proj_out + b
    const int PRED = BT * DIN, HID = BT * DM;
    float* predp = nullptr;
    float* hidp  = nullptr;
    if (out_size >= PRED + HID)      { predp = out; hidp = out + PRED; }
    else if (out_size == PRED)       { predp = out; }
    else                             { hidp = out; }

    layernorm_k<<<BT, 256, 0, STD>>>(
        p_h, p_o, p_o + (size_t)BT * DM,
        fn_w, fn_b, hidp ? hidp : p_hn, p_hn16, 0);
    if (predp) {
        cudaStreamWaitEvent(STD, g_sc.evPO, 0);
        tgemm_k<<<dim3((DIN + 127) / 128, BT / 128), 256, TG_SMEM, STD>>>(
            p_hn16, p_wpoh, p_wpol, proj_out_b, predp, DIN, DM);
    }
}